// round 4
// baseline (speedup 1.0000x reference)
#include <cuda_runtime.h>
#include <math.h>
#include <stdint.h>

// Problem constants
#define NNODES 40000
#define NEDGES 640000
#define ETOT   (NEDGES + NNODES)   // edges + appended self loops
#define HDIM   128

// ---------------------------------------------------------------------------
// Scratch (device globals; no allocation allowed in kernel_launch)
// ---------------------------------------------------------------------------
__device__ float g_buf0[(size_t)NNODES * HDIM];   // 20.5 MB
__device__ float g_buf1[(size_t)NNODES * HDIM];   // 20.5 MB
__device__ int   g_csr[ETOT];            // packed: col | (invalid << 31)
__device__ int   g_cnt[NNODES];
__device__ int   g_offs[NNODES + 1];
__device__ int   g_cur[NNODES];
__device__ float g_dinv[NNODES];
__device__ float g_acc[HDIM];
__device__ int   g_is64;

// ---------------------------------------------------------------------------
// Edge-index dtype detection: logically int64 [2,E] but may be int32
// physically (JAX x64 off). int32 data read as int64 packs two indices ->
// almost surely out of [0, NNODES) somewhere in the first 1024 slots.
// ---------------------------------------------------------------------------
__global__ void detect_dtype_kernel(const void* ei) {
    __shared__ int ok;
    if (threadIdx.x == 0) ok = 1;
    __syncthreads();
    const long long* p = (const long long*)ei;
    for (int i = threadIdx.x; i < 1024; i += blockDim.x) {
        long long v = p[i];
        if (v < 0 || v >= NNODES) atomicAnd(&ok, 0);
    }
    __syncthreads();
    if (threadIdx.x == 0) g_is64 = ok;
}

// ---------------------------------------------------------------------------
// CSR build (reads edge_index directly)
// ---------------------------------------------------------------------------
__global__ void cnt_init_kernel(int* cnt) {
    int i = blockIdx.x * blockDim.x + threadIdx.x;
    if (i < NNODES) cnt[i] = 1;     // appended self loop
}
__global__ void cnt_acc_kernel(const void* ei, int* cnt) {
    int e = blockIdx.x * blockDim.x + threadIdx.x;
    if (e >= NEDGES) return;
    int r = g_is64 ? (int)((const long long*)ei)[e] : ((const int*)ei)[e];
    atomicAdd(&cnt[r], 1);
}

// Single-block exclusive scan over NNODES counts.
__global__ __launch_bounds__(1024) void scan_kernel(
    const int* __restrict__ cnt, int* __restrict__ offs,
    int* __restrict__ cur, float* __restrict__ dinv)
{
    __shared__ int totals[1024];
    const int CH = (NNODES + 1023) / 1024;   // 40
    int t = threadIdx.x;
    int base = t * CH;
    int s = 0;
    for (int i = 0; i < CH; i++) {
        int idx = base + i;
        if (idx < NNODES) s += cnt[idx];
    }
    totals[t] = s;
    __syncthreads();
    for (int off = 1; off < 1024; off <<= 1) {
        int v = (t >= off) ? totals[t - off] : 0;
        __syncthreads();
        if (t >= off) totals[t] += v;
        __syncthreads();
    }
    int run = (t == 0) ? 0 : totals[t - 1];
    for (int i = 0; i < CH; i++) {
        int idx = base + i;
        if (idx < NNODES) {
            offs[idx] = run;
            cur[idx]  = run;
            int c = cnt[idx];
            dinv[idx] = rsqrtf((float)c);
            run += c;
        }
    }
    if (t == 0) offs[NNODES] = ETOT;
}

__global__ void csr_scatter_kernel(const void* ei, int* cur, int* csr) {
    int e = blockIdx.x * blockDim.x + threadIdx.x;
    if (e >= ETOT) return;
    int r, c, invalid = 0;
    if (e < NEDGES) {
        if (g_is64) {
            const long long* p = (const long long*)ei;
            r = (int)p[e]; c = (int)p[NEDGES + e];
        } else {
            const int* p = (const int*)ei;
            r = p[e]; c = p[NEDGES + e];
        }
        if (r == c) invalid = (int)0x80000000;  // masked for GAT, kept for GCN
    } else {
        r = c = e - NEDGES;
    }
    int pos = atomicAdd(&cur[r], 1);
    csr[pos] = c | invalid;
}

// ---------------------------------------------------------------------------
// tf32 tensor-core GEMM: C[M,128] = A[M,128] @ Weff[128,128] (+bias).
// Weff = W or W[0:128]+W[128:256] (ADDW2 folds concat([h,h])).
// 128 threads (4 warps, 2x2), warp tile 64x64, mma.m16n8k8 tf32.
// Both operands chunked through static smem (32 k per chunk, stride-40 pad)
// -> 40KB static smem, no dynamic-smem opt-in needed, 2 blocks/SM.
// kpos8 interleaves (k, k+4) adjacent so each fragment pair is one LDS.64.
// ---------------------------------------------------------------------------
#define KS_STRIDE 40   // floats per row in smem chunk tiles

__device__ __forceinline__ uint32_t f2tf32(float v) {
    uint32_t r;
    asm("cvt.rna.tf32.f32 %0, %1;" : "=r"(r) : "f"(v));
    return r;
}
__device__ __forceinline__ int kpos8(int k) {   // k in [0,32)
    return (k >> 3) * 8 + (k & 3) * 2 + ((k >> 2) & 1);
}
__device__ __forceinline__ void mma_tf32(float4& c, uint32_t a0, uint32_t a1,
                                         uint32_t a2, uint32_t a3,
                                         uint32_t b0, uint32_t b1) {
    asm volatile(
        "mma.sync.aligned.m16n8k8.row.col.f32.tf32.tf32.f32 "
        "{%0,%1,%2,%3}, {%4,%5,%6,%7}, {%8,%9}, {%0,%1,%2,%3};"
        : "+f"(c.x), "+f"(c.y), "+f"(c.z), "+f"(c.w)
        : "r"(a0), "r"(a1), "r"(a2), "r"(a3), "r"(b0), "r"(b1));
}

template<bool ADDW2, bool BIAS>
__global__ __launch_bounds__(128) void mm_tf32_k128(
    const float* __restrict__ A, const float* __restrict__ W,
    const float* __restrict__ bias, float* __restrict__ C, int M)
{
    __shared__ float Wp[128 * KS_STRIDE];   // [n=128][kpos 0..31]
    __shared__ float Ap[128 * KS_STRIDE];   // [m=128][kpos 0..31]

    const int t    = threadIdx.x;
    const int warp = t >> 5;
    const int lane = t & 31;
    const int gid  = lane >> 2;             // 0..7
    const int tg   = lane & 3;              // 0..3
    const int wm   = warp & 1;              // 2 warps along M
    const int wn   = warp >> 1;             // 2 warps along N
    const int m0   = blockIdx.x * 128;

    float4 c[4][8];
#pragma unroll
    for (int i = 0; i < 4; i++)
#pragma unroll
        for (int j = 0; j < 8; j++) c[i][j] = make_float4(0.f, 0.f, 0.f, 0.f);

    for (int ck = 0; ck < 4; ck++) {
        __syncthreads();
        // Stage W chunk: 32 k x 128 n (tf32-rounded, kpos8-interleaved)
        for (int i = t; i < 32 * 32; i += 128) {
            int kc = i >> 5;                 // 0..31 within chunk
            int n4 = (i & 31) << 2;
            int k  = ck * 32 + kc;
            float4 v = *(const float4*)&W[(size_t)k * 128 + n4];
            if (ADDW2) {
                float4 v2 = *(const float4*)&W[(size_t)(k + 128) * 128 + n4];
                v.x += v2.x; v.y += v2.y; v.z += v2.z; v.w += v2.w;
            }
            int kp = kpos8(kc);
            Wp[(size_t)(n4 + 0) * KS_STRIDE + kp] = __uint_as_float(f2tf32(v.x));
            Wp[(size_t)(n4 + 1) * KS_STRIDE + kp] = __uint_as_float(f2tf32(v.y));
            Wp[(size_t)(n4 + 2) * KS_STRIDE + kp] = __uint_as_float(f2tf32(v.z));
            Wp[(size_t)(n4 + 3) * KS_STRIDE + kp] = __uint_as_float(f2tf32(v.w));
        }
        // Stage A chunk: 128 rows x 32 k
        for (int i = t; i < 128 * 8; i += 128) {
            int m  = i >> 3;
            int k4 = (i & 7) << 2;
            float4 v = make_float4(0.f, 0.f, 0.f, 0.f);
            if (m0 + m < M)
                v = *(const float4*)&A[(size_t)(m0 + m) * 128 + ck * 32 + k4];
            float* ap = &Ap[(size_t)m * KS_STRIDE];
            ap[kpos8(k4 + 0)] = __uint_as_float(f2tf32(v.x));
            ap[kpos8(k4 + 1)] = __uint_as_float(f2tf32(v.y));
            ap[kpos8(k4 + 2)] = __uint_as_float(f2tf32(v.z));
            ap[kpos8(k4 + 3)] = __uint_as_float(f2tf32(v.w));
        }
        __syncthreads();

#pragma unroll
        for (int ks = 0; ks < 4; ks++) {
            const int kb = ks * 8 + tg * 2;
            // Preload B frags (8 n-tiles): b.x = W[k=tg][n], b.y = W[k=tg+4][n]
            uint32_t b0[8], b1[8];
#pragma unroll
            for (int nt = 0; nt < 8; nt++) {
                int col = wn * 64 + nt * 8 + gid;
                float2 b = *(const float2*)&Wp[(size_t)col * KS_STRIDE + kb];
                b0[nt] = __float_as_uint(b.x);
                b1[nt] = __float_as_uint(b.y);
            }
#pragma unroll
            for (int mt = 0; mt < 4; mt++) {
                int row = wm * 64 + mt * 16 + gid;
                float2 a02 = *(const float2*)&Ap[(size_t)row * KS_STRIDE + kb];
                float2 a13 = *(const float2*)&Ap[(size_t)(row + 8) * KS_STRIDE + kb];
                uint32_t a0 = __float_as_uint(a02.x);
                uint32_t a2 = __float_as_uint(a02.y);
                uint32_t a1 = __float_as_uint(a13.x);
                uint32_t a3 = __float_as_uint(a13.y);
#pragma unroll
                for (int nt = 0; nt < 8; nt++)
                    mma_tf32(c[mt][nt], a0, a1, a2, a3, b0[nt], b1[nt]);
            }
        }
    }

    // Epilogue: c.x,c.y -> (row, col:col+1), c.z,c.w -> (row+8, col:col+1)
#pragma unroll
    for (int mt = 0; mt < 4; mt++) {
        int r0 = m0 + wm * 64 + mt * 16 + gid;
#pragma unroll
        for (int nt = 0; nt < 8; nt++) {
            int col = wn * 64 + nt * 8 + tg * 2;
            float bx = 0.f, by = 0.f;
            if (BIAS) { bx = __ldg(&bias[col]); by = __ldg(&bias[col + 1]); }
            if (r0 < M) {
                float2 v = make_float2(c[mt][nt].x + bx, c[mt][nt].y + by);
                *(float2*)&C[(size_t)r0 * 128 + col] = v;
            }
            if (r0 + 8 < M) {
                float2 v = make_float2(c[mt][nt].z + bx, c[mt][nt].w + by);
                *(float2*)&C[(size_t)(r0 + 8) * 128 + col] = v;
            }
        }
    }
}

// ---------------------------------------------------------------------------
// GCN gather (warp per destination), unroll-4, fused bias + relu.
// ---------------------------------------------------------------------------
__global__ __launch_bounds__(256) void gcn_gather_kernel(
    const float* __restrict__ xw, const int* __restrict__ offs,
    const int* __restrict__ csr, const float* __restrict__ dinv,
    const float* __restrict__ bias, float* __restrict__ out)
{
    int node = (blockIdx.x * 256 + threadIdx.x) >> 5;
    int lane = threadIdx.x & 31;
    if (node >= NNODES) return;
    int s = __ldg(&offs[node]);
    int e = __ldg(&offs[node + 1]);
    float dr = __ldg(&dinv[node]);

    float4 A0 = make_float4(0.f,0.f,0.f,0.f), A1 = A0, A2 = A0, A3 = A0;
    int p = s;
    for (; p + 4 <= e; p += 4) {
        int c0 = __ldg(&csr[p + 0]) & 0x7fffffff;
        int c1 = __ldg(&csr[p + 1]) & 0x7fffffff;
        int c2 = __ldg(&csr[p + 2]) & 0x7fffffff;
        int c3 = __ldg(&csr[p + 3]) & 0x7fffffff;
        float n0 = dr * __ldg(&dinv[c0]);
        float n1 = dr * __ldg(&dinv[c1]);
        float n2 = dr * __ldg(&dinv[c2]);
        float n3 = dr * __ldg(&dinv[c3]);
        float4 v0 = *(const float4*)&xw[(size_t)c0 * 128 + lane * 4];
        float4 v1 = *(const float4*)&xw[(size_t)c1 * 128 + lane * 4];
        float4 v2 = *(const float4*)&xw[(size_t)c2 * 128 + lane * 4];
        float4 v3 = *(const float4*)&xw[(size_t)c3 * 128 + lane * 4];
        A0.x = fmaf(v0.x,n0,A0.x); A0.y = fmaf(v0.y,n0,A0.y); A0.z = fmaf(v0.z,n0,A0.z); A0.w = fmaf(v0.w,n0,A0.w);
        A1.x = fmaf(v1.x,n1,A1.x); A1.y = fmaf(v1.y,n1,A1.y); A1.z = fmaf(v1.z,n1,A1.z); A1.w = fmaf(v1.w,n1,A1.w);
        A2.x = fmaf(v2.x,n2,A2.x); A2.y = fmaf(v2.y,n2,A2.y); A2.z = fmaf(v2.z,n2,A2.z); A2.w = fmaf(v2.w,n2,A2.w);
        A3.x = fmaf(v3.x,n3,A3.x); A3.y = fmaf(v3.y,n3,A3.y); A3.z = fmaf(v3.z,n3,A3.z); A3.w = fmaf(v3.w,n3,A3.w);
    }
    for (; p < e; p++) {
        int c0 = __ldg(&csr[p]) & 0x7fffffff;
        float n0 = dr * __ldg(&dinv[c0]);
        float4 v0 = *(const float4*)&xw[(size_t)c0 * 128 + lane * 4];
        A0.x = fmaf(v0.x,n0,A0.x); A0.y = fmaf(v0.y,n0,A0.y); A0.z = fmaf(v0.z,n0,A0.z); A0.w = fmaf(v0.w,n0,A0.w);
    }
    float4 acc;
    acc.x = (A0.x + A1.x) + (A2.x + A3.x);
    acc.y = (A0.y + A1.y) + (A2.y + A3.y);
    acc.z = (A0.z + A1.z) + (A2.z + A3.z);
    acc.w = (A0.w + A1.w) + (A2.w + A3.w);
    float4 b = *(const float4*)&bias[lane * 4];
    acc.x = fmaxf(acc.x + b.x, 0.0f);
    acc.y = fmaxf(acc.y + b.y, 0.0f);
    acc.z = fmaxf(acc.z + b.z, 0.0f);
    acc.w = fmaxf(acc.w + b.w, 0.0f);
    *(float4*)&out[(size_t)node * 128 + lane * 4] = acc;
}

// ---------------------------------------------------------------------------
// GAT gather: warp per destination, TWO interleaved online-softmax states
// (merged at the end) -> 2x MLP and half the serial shfl chain.
// ---------------------------------------------------------------------------
__device__ __forceinline__ float warp_dot(float4 a, float4 b) {
    float d = a.x*b.x + a.y*b.y + a.z*b.z + a.w*b.w;
#pragma unroll
    for (int s = 16; s; s >>= 1) d += __shfl_xor_sync(0xffffffffu, d, s);
    return d;
}

__global__ __launch_bounds__(256) void gat_gather_kernel(
    const float* __restrict__ h, const int* __restrict__ offs,
    const int* __restrict__ csr, float* __restrict__ out)
{
    int node = (blockIdx.x * 256 + threadIdx.x) >> 5;
    int lane = threadIdx.x & 31;
    if (node >= NNODES) return;
    int s = __ldg(&offs[node]);
    int e = __ldg(&offs[node + 1]);

    float4 hr = *(const float4*)&h[(size_t)node * 128 + lane * 4];

    float m0 = -INFINITY, d0 = 0.0f;
    float m1 = -INFINITY, d1 = 0.0f;
    float4 a0 = make_float4(0.f,0.f,0.f,0.f), a1 = a0;

    int p = s;
    for (; p + 2 <= e; p += 2) {
        int r0 = __ldg(&csr[p]);
        int r1 = __ldg(&csr[p + 1]);
        float4 h0 = *(const float4*)&h[(size_t)(r0 & 0x7fffffff) * 128 + lane * 4];
        float4 h1 = *(const float4*)&h[(size_t)(r1 & 0x7fffffff) * 128 + lane * 4];
        float t0 = h0.x*hr.x + h0.y*hr.y + h0.z*hr.z + h0.w*hr.w;
        float t1 = h1.x*hr.x + h1.y*hr.y + h1.z*hr.z + h1.w*hr.w;
#pragma unroll
        for (int sh = 16; sh; sh >>= 1) {
            t0 += __shfl_xor_sync(0xffffffffu, t0, sh);
            t1 += __shfl_xor_sync(0xffffffffu, t1, sh);
        }
        if (r0 >= 0) {
            float al = (t0 >= 0.f) ? t0 : 0.2f * t0;
            if (al > m0) {
                float sc = __expf(m0 - al);
                d0 *= sc; a0.x *= sc; a0.y *= sc; a0.z *= sc; a0.w *= sc;
                m0 = al;
            }
            float w = __expf(al - m0);
            d0 += w;
            a0.x = fmaf(h0.x,w,a0.x); a0.y = fmaf(h0.y,w,a0.y);
            a0.z = fmaf(h0.z,w,a0.z); a0.w = fmaf(h0.w,w,a0.w);
        }
        if (r1 >= 0) {
            float al = (t1 >= 0.f) ? t1 : 0.2f * t1;
            if (al > m1) {
                float sc = __expf(m1 - al);
                d1 *= sc; a1.x *= sc; a1.y *= sc; a1.z *= sc; a1.w *= sc;
                m1 = al;
            }
            float w = __expf(al - m1);
            d1 += w;
            a1.x = fmaf(h1.x,w,a1.x); a1.y = fmaf(h1.y,w,a1.y);
            a1.z = fmaf(h1.z,w,a1.z); a1.w = fmaf(h1.w,w,a1.w);
        }
    }
    if (p < e) {
        int r0 = __ldg(&csr[p]);
        float4 h0 = *(const float4*)&h[(size_t)(r0 & 0x7fffffff) * 128 + lane * 4];
        float t0 = warp_dot(hr, h0);
        if (r0 >= 0) {
            float al = (t0 >= 0.f) ? t0 : 0.2f * t0;
            if (al > m0) {
                float sc = __expf(m0 - al);
                d0 *= sc; a0.x *= sc; a0.y *= sc; a0.z *= sc; a0.w *= sc;
                m0 = al;
            }
            float w = __expf(al - m0);
            d0 += w;
            a0.x = fmaf(h0.x,w,a0.x); a0.y = fmaf(h0.y,w,a0.y);
            a0.z = fmaf(h0.z,w,a0.z); a0.w = fmaf(h0.w,w,a0.w);
        }
    }

    // Merge the two states (at least one is non-empty: self loop always valid)
    float M_ = fmaxf(m0, m1);
    float s0 = __expf(m0 - M_);
    float s1 = __expf(m1 - M_);
    float den = d0 * s0 + d1 * s1;
    float4 acc;
    acc.x = a0.x * s0 + a1.x * s1;
    acc.y = a0.y * s0 + a1.y * s1;
    acc.z = a0.z * s0 + a1.z * s1;
    acc.w = a0.w * s0 + a1.w * s1;
    float inv = 1.0f / fmaxf(den, 1e-16f);
    acc.x *= inv; acc.y *= inv; acc.z *= inv; acc.w *= inv;
    *(float4*)&out[(size_t)node * 128 + lane * 4] = acc;
}

// ---------------------------------------------------------------------------
// Global mean pool
// ---------------------------------------------------------------------------
__global__ void colsum_kernel(const float* __restrict__ h, float* __restrict__ acc)
{
    int col = threadIdx.x;                 // 128 threads
    int r0   = blockIdx.x * 256;
    int rend = r0 + 256;
    if (rend > NNODES) rend = NNODES;
    float s = 0.0f;
    for (int r = r0; r < rend; r++) s += h[(size_t)r * 128 + col];
    atomicAdd(&acc[col], s);
}

__global__ void writeout_kernel(const float* __restrict__ acc, float* __restrict__ out)
{
    int i = threadIdx.x;                   // 256 threads
    out[i] = acc[i & 127] * (1.0f / (float)NNODES);
}

// ---------------------------------------------------------------------------
// Launch
// ---------------------------------------------------------------------------
extern "C" void kernel_launch(void* const* d_in, const int* in_sizes, int n_in,
                              void* d_out, int out_size)
{
    const float* x  = (const float*)d_in[0];
    const void*  ei = d_in[1];
    const float* Wg[3] = {(const float*)d_in[2], (const float*)d_in[6],  (const float*)d_in[10]};
    const float* bg[3] = {(const float*)d_in[3], (const float*)d_in[7],  (const float*)d_in[11]};
    const float* Wa[3] = {(const float*)d_in[4], (const float*)d_in[8],  (const float*)d_in[12]};
    const float* ba[3] = {(const float*)d_in[5], (const float*)d_in[9],  (const float*)d_in[13]};

    float *buf0, *buf1, *dinv, *acc;
    int *csr, *cnt, *offs, *cur;
    cudaGetSymbolAddress((void**)&buf0, g_buf0);
    cudaGetSymbolAddress((void**)&buf1, g_buf1);
    cudaGetSymbolAddress((void**)&dinv, g_dinv);
    cudaGetSymbolAddress((void**)&acc,  g_acc);
    cudaGetSymbolAddress((void**)&csr,  g_csr);
    cudaGetSymbolAddress((void**)&cnt,  g_cnt);
    cudaGetSymbolAddress((void**)&offs, g_offs);
    cudaGetSymbolAddress((void**)&cur,  g_cur);

    const int NB_N    = (NNODES + 255) / 256;
    const int NB_E    = (NEDGES + 255) / 256;
    const int NB_ET   = (ETOT + 255) / 256;
    const int NB_WARP = (NNODES + 7) / 8;        // warp-per-node, 8 warps/block
    const int NB_GEMM = (NNODES + 127) / 128;    // 313
    const int NB_COL  = (NNODES + 255) / 256;

    // CSR build
    detect_dtype_kernel<<<1, 256>>>(ei);
    cnt_init_kernel<<<NB_N, 256>>>(cnt);
    cnt_acc_kernel<<<NB_E, 256>>>(ei, cnt);
    scan_kernel<<<1, 1024>>>(cnt, offs, cur, dinv);
    csr_scatter_kernel<<<NB_ET, 256>>>(ei, cur, csr);

    for (int l = 0; l < 3; l++) {
        // --- GCN: GEMM -> gather(+bias+relu) ---
        if (l == 0)
            mm_tf32_k128<false,false><<<NB_GEMM, 128>>>(x,    Wg[l], nullptr, buf1, NNODES);
        else
            mm_tf32_k128<true, false><<<NB_GEMM, 128>>>(buf0, Wg[l], nullptr, buf1, NNODES);
        gcn_gather_kernel<<<NB_WARP, 256>>>(buf1, offs, csr, dinv, bg[l], buf0);

        // --- GAT: GEMM(+bias) -> fused online-softmax gather ---
        mm_tf32_k128<false,true><<<NB_GEMM, 128>>>(buf0, Wa[l], ba[l], buf1, NNODES);
        gat_gather_kernel<<<NB_WARP, 256>>>(buf1, offs, csr, buf0);
    }

    // Global mean pool (concat halves identical)
    cudaMemsetAsync(acc, 0, HDIM * sizeof(float), 0);
    colsum_kernel<<<NB_COL, 128>>>(buf0, acc);
    writeout_kernel<<<1, 256>>>(acc, (float*)d_out);
}

// round 5
// speedup vs baseline: 1.4036x; 1.4036x over previous
#include <cuda_runtime.h>
#include <math.h>
#include <stdint.h>

// Problem constants
#define NNODES 40000
#define NEDGES 640000
#define ETOT   (NEDGES + NNODES)   // edges + appended self loops
#define HDIM   128
#define SCAN_NB 40                 // ceil(NNODES / 1024)

// ---------------------------------------------------------------------------
// Scratch (device globals; no allocation allowed in kernel_launch)
// ---------------------------------------------------------------------------
__device__ float g_buf0[(size_t)NNODES * HDIM];   // 20.5 MB
__device__ float g_buf1[(size_t)NNODES * HDIM];   // 20.5 MB
__device__ int   g_csr[ETOT];            // packed: col | (invalid << 31)
__device__ int   g_cnt[NNODES];          // edge count per row (excl. self loop)
__device__ int   g_offs[NNODES + 1];
__device__ int   g_cur[NNODES];
__device__ int   g_bsum[64];
__device__ float g_dinv[NNODES];
__device__ float g_acc[HDIM];
__device__ float g_wprep[6 * 128 * 32 * 4];  // 6 tf32-interleaved Weff, 393KB
__device__ int   g_is64;

// ---------------------------------------------------------------------------
// Edge-index dtype detection: logically int64 [2,E] but may be int32
// physically (JAX x64 off). int32 data read as int64 packs two indices ->
// almost surely out of [0, NNODES) somewhere in the first 1024 slots.
// ---------------------------------------------------------------------------
__global__ void detect_dtype_kernel(const void* ei) {
    __shared__ int ok;
    if (threadIdx.x == 0) ok = 1;
    __syncthreads();
    const long long* p = (const long long*)ei;
    for (int i = threadIdx.x; i < 1024; i += blockDim.x) {
        long long v = p[i];
        if (v < 0 || v >= NNODES) atomicAnd(&ok, 0);
    }
    __syncthreads();
    if (threadIdx.x == 0) g_is64 = ok;
}

// ---------------------------------------------------------------------------
// CSR build
// ---------------------------------------------------------------------------
__global__ void cnt_acc_kernel(const void* ei, int* cnt) {
    int e = blockIdx.x * blockDim.x + threadIdx.x;
    if (e >= NEDGES) return;
    int r = g_is64 ? (int)((const long long*)ei)[e] : ((const int*)ei)[e];
    atomicAdd(&cnt[r], 1);
}

// Phase 1: per-block (1024 elems) exclusive scan of deg = cnt+1; block totals.
__global__ __launch_bounds__(1024) void scan1_kernel(
    const int* __restrict__ cnt, int* __restrict__ excl, int* __restrict__ bsum)
{
    __shared__ int wsum[32];
    int t = threadIdx.x;
    int i = blockIdx.x * 1024 + t;
    int lane = t & 31, w = t >> 5;
    int v = (i < NNODES) ? (cnt[i] + 1) : 0;    // +1 = appended self loop
    int s = v;
#pragma unroll
    for (int d = 1; d < 32; d <<= 1) {
        int u = __shfl_up_sync(0xffffffffu, s, d);
        if (lane >= d) s += u;
    }
    if (lane == 31) wsum[w] = s;
    __syncthreads();
    if (w == 0) {
        int ws = wsum[lane];
#pragma unroll
        for (int d = 1; d < 32; d <<= 1) {
            int u = __shfl_up_sync(0xffffffffu, ws, d);
            if (lane >= d) ws += u;
        }
        wsum[lane] = ws;
    }
    __syncthreads();
    int incl = s + (w ? wsum[w - 1] : 0);
    if (i < NNODES) excl[i] = incl - v;          // exclusive within block
    if (t == 0) bsum[blockIdx.x] = wsum[31];     // block total
}

// Phase 2: exclusive scan of SCAN_NB block totals (single block).
__global__ void scan2_kernel(int* bsum) {
    __shared__ int sm[SCAN_NB];
    int t = threadIdx.x;
    if (t < SCAN_NB) sm[t] = bsum[t];
    __syncthreads();
    if (t == 0) {
        int run = 0;
        for (int b = 0; b < SCAN_NB; b++) {
            int v = sm[b];
            sm[b] = run;
            run += v;
        }
    }
    __syncthreads();
    if (t < SCAN_NB) bsum[t] = sm[t];
}

// Phase 3: finalize offsets, write cur and dinv.
__global__ __launch_bounds__(1024) void scan3_kernel(
    const int* __restrict__ cnt, const int* __restrict__ bsum,
    int* __restrict__ offs, int* __restrict__ cur, float* __restrict__ dinv)
{
    int i = blockIdx.x * 1024 + threadIdx.x;
    if (i < NNODES) {
        int off = offs[i] + bsum[blockIdx.x];    // offs held within-block excl
        offs[i] = off;
        cur[i]  = off;
        dinv[i] = rsqrtf((float)(cnt[i] + 1));
    }
    if (i == 0) offs[NNODES] = ETOT;
}

__global__ void csr_scatter_kernel(const void* ei, int* cur, int* csr) {
    int e = blockIdx.x * blockDim.x + threadIdx.x;
    if (e >= ETOT) return;
    int r, c, invalid = 0;
    if (e < NEDGES) {
        if (g_is64) {
            const long long* p = (const long long*)ei;
            r = (int)p[e]; c = (int)p[NEDGES + e];
        } else {
            const int* p = (const int*)ei;
            r = p[e]; c = p[NEDGES + e];
        }
        if (r == c) invalid = (int)0x80000000;  // masked for GAT, kept for GCN
    } else {
        r = c = e - NEDGES;
    }
    int pos = atomicAdd(&cur[r], 1);
    csr[pos] = c | invalid;
}

// ---------------------------------------------------------------------------
// Weight prep: all 6 effective weights -> tf32, kpos8-interleaved, once.
// Layout: g_wprep[((mat*4 + ck)*128 + n)*32 + kpos8(k&31)].
// mats: 0=Wg0, 1=Wa0, 2=Wg1(+fold), 3=Wa1, 4=Wg2(+fold), 5=Wa2
// ---------------------------------------------------------------------------
__device__ __forceinline__ uint32_t f2tf32(float v) {
    uint32_t r;
    asm("cvt.rna.tf32.f32 %0, %1;" : "=r"(r) : "f"(v));
    return r;
}
__device__ __forceinline__ int kpos8(int k) {   // k in [0,32)
    return (k >> 3) * 8 + (k & 3) * 2 + ((k >> 2) & 1);
}

__global__ void wprep_kernel(const float* Wg0, const float* Wa0,
                             const float* Wg1, const float* Wa1,
                             const float* Wg2, const float* Wa2,
                             float* out)
{
    int m = blockIdx.x;
    const float* W; bool add;
    switch (m) {
        case 0: W = Wg0; add = false; break;
        case 1: W = Wa0; add = false; break;
        case 2: W = Wg1; add = true;  break;
        case 3: W = Wa1; add = false; break;
        case 4: W = Wg2; add = true;  break;
        default: W = Wa2; add = false; break;
    }
    for (int i = threadIdx.x; i < 128 * 128; i += blockDim.x) {
        int n = i & 127, k = i >> 7;
        float v = W[(size_t)k * 128 + n];
        if (add) v += W[(size_t)(k + 128) * 128 + n];
        int ck = k >> 5, kp = kpos8(k & 31);
        out[(((size_t)(m * 4 + ck) * 128 + n) * 32) + kp] = __uint_as_float(f2tf32(v));
    }
}

// ---------------------------------------------------------------------------
// tf32 tensor-core GEMM: C[M,128] = A[M,128] @ Weff[128,128] (+bias).
// 256 threads (8 warps, 2 along M x 4 along N), warp tile 64x32.
// W staged from pre-interleaved g_wprep (pure float4 copies); A converted
// on the fly. 40KB static smem -> 2 blocks/SM.
// ---------------------------------------------------------------------------
#define KS_STRIDE 40

__device__ __forceinline__ void mma_tf32(float4& c, uint32_t a0, uint32_t a1,
                                         uint32_t a2, uint32_t a3,
                                         uint32_t b0, uint32_t b1) {
    asm volatile(
        "mma.sync.aligned.m16n8k8.row.col.f32.tf32.tf32.f32 "
        "{%0,%1,%2,%3}, {%4,%5,%6,%7}, {%8,%9}, {%0,%1,%2,%3};"
        : "+f"(c.x), "+f"(c.y), "+f"(c.z), "+f"(c.w)
        : "r"(a0), "r"(a1), "r"(a2), "r"(a3), "r"(b0), "r"(b1));
}

template<bool BIAS>
__global__ __launch_bounds__(256) void mm_tf32_k128(
    const float* __restrict__ A, const float* __restrict__ wprep, int mat,
    const float* __restrict__ bias, float* __restrict__ C, int M)
{
    __shared__ float Wp[128 * KS_STRIDE];   // [n=128][kpos 0..31]
    __shared__ float Ap[128 * KS_STRIDE];   // [m=128][kpos 0..31]

    const int t    = threadIdx.x;
    const int warp = t >> 5;
    const int lane = t & 31;
    const int gid  = lane >> 2;             // 0..7
    const int tg   = lane & 3;              // 0..3
    const int wm   = warp & 1;              // 2 warps along M (64 rows each)
    const int wn   = warp >> 1;             // 4 warps along N (32 cols each)
    const int m0   = blockIdx.x * 128;

    float4 c[4][4];
#pragma unroll
    for (int i = 0; i < 4; i++)
#pragma unroll
        for (int j = 0; j < 4; j++) c[i][j] = make_float4(0.f, 0.f, 0.f, 0.f);

    for (int ck = 0; ck < 4; ck++) {
        __syncthreads();
        // Stage W chunk: pre-interleaved, pure float4 copies (4 iters)
        const float* wsrc = wprep + ((size_t)(mat * 4 + ck) * 128) * 32;
        for (int i = t; i < 1024; i += 256) {
            int n   = i >> 3;
            int kp4 = (i & 7) << 2;
            *(float4*)&Wp[(size_t)n * KS_STRIDE + kp4] =
                *(const float4*)&wsrc[(size_t)n * 32 + kp4];
        }
        // Stage A chunk: 128 rows x 32 k, tf32-rounded + interleaved (4 iters)
        for (int i = t; i < 1024; i += 256) {
            int m  = i >> 3;
            int k4 = (i & 7) << 2;
            float4 v = make_float4(0.f, 0.f, 0.f, 0.f);
            if (m0 + m < M)
                v = *(const float4*)&A[(size_t)(m0 + m) * 128 + ck * 32 + k4];
            float* ap = &Ap[(size_t)m * KS_STRIDE];
            ap[kpos8(k4 + 0)] = __uint_as_float(f2tf32(v.x));
            ap[kpos8(k4 + 1)] = __uint_as_float(f2tf32(v.y));
            ap[kpos8(k4 + 2)] = __uint_as_float(f2tf32(v.z));
            ap[kpos8(k4 + 3)] = __uint_as_float(f2tf32(v.w));
        }
        __syncthreads();

#pragma unroll
        for (int ks = 0; ks < 4; ks++) {
            const int kb = ks * 8 + tg * 2;
            uint32_t b0[4], b1[4];
#pragma unroll
            for (int nt = 0; nt < 4; nt++) {
                int col = wn * 32 + nt * 8 + gid;
                float2 b = *(const float2*)&Wp[(size_t)col * KS_STRIDE + kb];
                b0[nt] = __float_as_uint(b.x);
                b1[nt] = __float_as_uint(b.y);
            }
#pragma unroll
            for (int mt = 0; mt < 4; mt++) {
                int row = wm * 64 + mt * 16 + gid;
                float2 a02 = *(const float2*)&Ap[(size_t)row * KS_STRIDE + kb];
                float2 a13 = *(const float2*)&Ap[(size_t)(row + 8) * KS_STRIDE + kb];
                uint32_t a0 = __float_as_uint(a02.x);
                uint32_t a2 = __float_as_uint(a02.y);
                uint32_t a1 = __float_as_uint(a13.x);
                uint32_t a3 = __float_as_uint(a13.y);
#pragma unroll
                for (int nt = 0; nt < 4; nt++)
                    mma_tf32(c[mt][nt], a0, a1, a2, a3, b0[nt], b1[nt]);
            }
        }
    }

    // Epilogue
#pragma unroll
    for (int mt = 0; mt < 4; mt++) {
        int r0 = m0 + wm * 64 + mt * 16 + gid;
#pragma unroll
        for (int nt = 0; nt < 4; nt++) {
            int col = wn * 32 + nt * 8 + tg * 2;
            float bx = 0.f, by = 0.f;
            if (BIAS) { bx = __ldg(&bias[col]); by = __ldg(&bias[col + 1]); }
            if (r0 < M) {
                float2 v = make_float2(c[mt][nt].x + bx, c[mt][nt].y + by);
                *(float2*)&C[(size_t)r0 * 128 + col] = v;
            }
            if (r0 + 8 < M) {
                float2 v = make_float2(c[mt][nt].z + bx, c[mt][nt].w + by);
                *(float2*)&C[(size_t)(r0 + 8) * 128 + col] = v;
            }
        }
    }
}

// ---------------------------------------------------------------------------
// GCN gather (warp per destination), unroll-4, fused bias + relu.
// ---------------------------------------------------------------------------
__global__ __launch_bounds__(256) void gcn_gather_kernel(
    const float* __restrict__ xw, const int* __restrict__ offs,
    const int* __restrict__ csr, const float* __restrict__ dinv,
    const float* __restrict__ bias, float* __restrict__ out)
{
    int node = (blockIdx.x * 256 + threadIdx.x) >> 5;
    int lane = threadIdx.x & 31;
    if (node >= NNODES) return;
    int s = __ldg(&offs[node]);
    int e = __ldg(&offs[node + 1]);
    float dr = __ldg(&dinv[node]);

    float4 A0 = make_float4(0.f,0.f,0.f,0.f), A1 = A0, A2 = A0, A3 = A0;
    int p = s;
    for (; p + 4 <= e; p += 4) {
        int c0 = __ldg(&csr[p + 0]) & 0x7fffffff;
        int c1 = __ldg(&csr[p + 1]) & 0x7fffffff;
        int c2 = __ldg(&csr[p + 2]) & 0x7fffffff;
        int c3 = __ldg(&csr[p + 3]) & 0x7fffffff;
        float n0 = dr * __ldg(&dinv[c0]);
        float n1 = dr * __ldg(&dinv[c1]);
        float n2 = dr * __ldg(&dinv[c2]);
        float n3 = dr * __ldg(&dinv[c3]);
        float4 v0 = *(const float4*)&xw[(size_t)c0 * 128 + lane * 4];
        float4 v1 = *(const float4*)&xw[(size_t)c1 * 128 + lane * 4];
        float4 v2 = *(const float4*)&xw[(size_t)c2 * 128 + lane * 4];
        float4 v3 = *(const float4*)&xw[(size_t)c3 * 128 + lane * 4];
        A0.x = fmaf(v0.x,n0,A0.x); A0.y = fmaf(v0.y,n0,A0.y); A0.z = fmaf(v0.z,n0,A0.z); A0.w = fmaf(v0.w,n0,A0.w);
        A1.x = fmaf(v1.x,n1,A1.x); A1.y = fmaf(v1.y,n1,A1.y); A1.z = fmaf(v1.z,n1,A1.z); A1.w = fmaf(v1.w,n1,A1.w);
        A2.x = fmaf(v2.x,n2,A2.x); A2.y = fmaf(v2.y,n2,A2.y); A2.z = fmaf(v2.z,n2,A2.z); A2.w = fmaf(v2.w,n2,A2.w);
        A3.x = fmaf(v3.x,n3,A3.x); A3.y = fmaf(v3.y,n3,A3.y); A3.z = fmaf(v3.z,n3,A3.z); A3.w = fmaf(v3.w,n3,A3.w);
    }
    for (; p < e; p++) {
        int c0 = __ldg(&csr[p]) & 0x7fffffff;
        float n0 = dr * __ldg(&dinv[c0]);
        float4 v0 = *(const float4*)&xw[(size_t)c0 * 128 + lane * 4];
        A0.x = fmaf(v0.x,n0,A0.x); A0.y = fmaf(v0.y,n0,A0.y); A0.z = fmaf(v0.z,n0,A0.z); A0.w = fmaf(v0.w,n0,A0.w);
    }
    float4 acc;
    acc.x = (A0.x + A1.x) + (A2.x + A3.x);
    acc.y = (A0.y + A1.y) + (A2.y + A3.y);
    acc.z = (A0.z + A1.z) + (A2.z + A3.z);
    acc.w = (A0.w + A1.w) + (A2.w + A3.w);
    float4 b = *(const float4*)&bias[lane * 4];
    acc.x = fmaxf(acc.x + b.x, 0.0f);
    acc.y = fmaxf(acc.y + b.y, 0.0f);
    acc.z = fmaxf(acc.z + b.z, 0.0f);
    acc.w = fmaxf(acc.w + b.w, 0.0f);
    *(float4*)&out[(size_t)node * 128 + lane * 4] = acc;
}

// ---------------------------------------------------------------------------
// GAT gather: warp per destination, TWO interleaved online-softmax states.
// ---------------------------------------------------------------------------
__device__ __forceinline__ float warp_dot(float4 a, float4 b) {
    float d = a.x*b.x + a.y*b.y + a.z*b.z + a.w*b.w;
#pragma unroll
    for (int s = 16; s; s >>= 1) d += __shfl_xor_sync(0xffffffffu, d, s);
    return d;
}

__global__ __launch_bounds__(256) void gat_gather_kernel(
    const float* __restrict__ h, const int* __restrict__ offs,
    const int* __restrict__ csr, float* __restrict__ out)
{
    int node = (blockIdx.x * 256 + threadIdx.x) >> 5;
    int lane = threadIdx.x & 31;
    if (node >= NNODES) return;
    int s = __ldg(&offs[node]);
    int e = __ldg(&offs[node + 1]);

    float4 hr = *(const float4*)&h[(size_t)node * 128 + lane * 4];

    float m0 = -INFINITY, d0 = 0.0f;
    float m1 = -INFINITY, d1 = 0.0f;
    float4 a0 = make_float4(0.f,0.f,0.f,0.f), a1 = a0;

    int p = s;
    for (; p + 2 <= e; p += 2) {
        int r0 = __ldg(&csr[p]);
        int r1 = __ldg(&csr[p + 1]);
        float4 h0 = *(const float4*)&h[(size_t)(r0 & 0x7fffffff) * 128 + lane * 4];
        float4 h1 = *(const float4*)&h[(size_t)(r1 & 0x7fffffff) * 128 + lane * 4];
        float t0 = h0.x*hr.x + h0.y*hr.y + h0.z*hr.z + h0.w*hr.w;
        float t1 = h1.x*hr.x + h1.y*hr.y + h1.z*hr.z + h1.w*hr.w;
#pragma unroll
        for (int sh = 16; sh; sh >>= 1) {
            t0 += __shfl_xor_sync(0xffffffffu, t0, sh);
            t1 += __shfl_xor_sync(0xffffffffu, t1, sh);
        }
        if (r0 >= 0) {
            float al = (t0 >= 0.f) ? t0 : 0.2f * t0;
            if (al > m0) {
                float sc = __expf(m0 - al);
                d0 *= sc; a0.x *= sc; a0.y *= sc; a0.z *= sc; a0.w *= sc;
                m0 = al;
            }
            float w = __expf(al - m0);
            d0 += w;
            a0.x = fmaf(h0.x,w,a0.x); a0.y = fmaf(h0.y,w,a0.y);
            a0.z = fmaf(h0.z,w,a0.z); a0.w = fmaf(h0.w,w,a0.w);
        }
        if (r1 >= 0) {
            float al = (t1 >= 0.f) ? t1 : 0.2f * t1;
            if (al > m1) {
                float sc = __expf(m1 - al);
                d1 *= sc; a1.x *= sc; a1.y *= sc; a1.z *= sc; a1.w *= sc;
                m1 = al;
            }
            float w = __expf(al - m1);
            d1 += w;
            a1.x = fmaf(h1.x,w,a1.x); a1.y = fmaf(h1.y,w,a1.y);
            a1.z = fmaf(h1.z,w,a1.z); a1.w = fmaf(h1.w,w,a1.w);
        }
    }
    if (p < e) {
        int r0 = __ldg(&csr[p]);
        float4 h0 = *(const float4*)&h[(size_t)(r0 & 0x7fffffff) * 128 + lane * 4];
        float t0 = warp_dot(hr, h0);
        if (r0 >= 0) {
            float al = (t0 >= 0.f) ? t0 : 0.2f * t0;
            if (al > m0) {
                float sc = __expf(m0 - al);
                d0 *= sc; a0.x *= sc; a0.y *= sc; a0.z *= sc; a0.w *= sc;
                m0 = al;
            }
            float w = __expf(al - m0);
            d0 += w;
            a0.x = fmaf(h0.x,w,a0.x); a0.y = fmaf(h0.y,w,a0.y);
            a0.z = fmaf(h0.z,w,a0.z); a0.w = fmaf(h0.w,w,a0.w);
        }
    }

    float M_ = fmaxf(m0, m1);
    float s0 = __expf(m0 - M_);
    float s1 = __expf(m1 - M_);
    float den = d0 * s0 + d1 * s1;
    float4 acc;
    acc.x = a0.x * s0 + a1.x * s1;
    acc.y = a0.y * s0 + a1.y * s1;
    acc.z = a0.z * s0 + a1.z * s1;
    acc.w = a0.w * s0 + a1.w * s1;
    float inv = 1.0f / fmaxf(den, 1e-16f);
    acc.x *= inv; acc.y *= inv; acc.z *= inv; acc.w *= inv;
    *(float4*)&out[(size_t)node * 128 + lane * 4] = acc;
}

// ---------------------------------------------------------------------------
// Global mean pool
// ---------------------------------------------------------------------------
__global__ void colsum_kernel(const float* __restrict__ h, float* __restrict__ acc)
{
    int col = threadIdx.x;                 // 128 threads
    int r0   = blockIdx.x * 256;
    int rend = r0 + 256;
    if (rend > NNODES) rend = NNODES;
    float s = 0.0f;
    for (int r = r0; r < rend; r++) s += h[(size_t)r * 128 + col];
    atomicAdd(&acc[col], s);
}

__global__ void writeout_kernel(const float* __restrict__ acc, float* __restrict__ out)
{
    int i = threadIdx.x;                   // 256 threads
    out[i] = acc[i & 127] * (1.0f / (float)NNODES);
}

// ---------------------------------------------------------------------------
// Launch
// ---------------------------------------------------------------------------
extern "C" void kernel_launch(void* const* d_in, const int* in_sizes, int n_in,
                              void* d_out, int out_size)
{
    const float* x  = (const float*)d_in[0];
    const void*  ei = d_in[1];
    const float* Wg[3] = {(const float*)d_in[2], (const float*)d_in[6],  (const float*)d_in[10]};
    const float* bg[3] = {(const float*)d_in[3], (const float*)d_in[7],  (const float*)d_in[11]};
    const float* Wa[3] = {(const float*)d_in[4], (const float*)d_in[8],  (const float*)d_in[12]};
    const float* ba[3] = {(const float*)d_in[5], (const float*)d_in[9],  (const float*)d_in[13]};

    float *buf0, *buf1, *dinv, *acc, *wprep;
    int *csr, *cnt, *offs, *cur, *bsum;
    cudaGetSymbolAddress((void**)&buf0, g_buf0);
    cudaGetSymbolAddress((void**)&buf1, g_buf1);
    cudaGetSymbolAddress((void**)&dinv, g_dinv);
    cudaGetSymbolAddress((void**)&acc,  g_acc);
    cudaGetSymbolAddress((void**)&wprep,g_wprep);
    cudaGetSymbolAddress((void**)&csr,  g_csr);
    cudaGetSymbolAddress((void**)&cnt,  g_cnt);
    cudaGetSymbolAddress((void**)&offs, g_offs);
    cudaGetSymbolAddress((void**)&cur,  g_cur);
    cudaGetSymbolAddress((void**)&bsum, g_bsum);

    const int NB_E    = (NEDGES + 255) / 256;
    const int NB_ET   = (ETOT + 255) / 256;
    const int NB_WARP = (NNODES + 7) / 8;        // warp-per-node, 8 warps/block
    const int NB_GEMM = (NNODES + 127) / 128;    // 313
    const int NB_COL  = (NNODES + 255) / 256;

    // Weight prep (independent of everything else)
    wprep_kernel<<<6, 256>>>(Wg[0], Wa[0], Wg[1], Wa[1], Wg[2], Wa[2], wprep);

    // CSR build (parallel scan)
    detect_dtype_kernel<<<1, 256>>>(ei);
    cudaMemsetAsync(cnt, 0, NNODES * sizeof(int), 0);
    cnt_acc_kernel<<<NB_E, 256>>>(ei, cnt);
    scan1_kernel<<<SCAN_NB, 1024>>>(cnt, offs, bsum);
    scan2_kernel<<<1, 64>>>(bsum);
    scan3_kernel<<<SCAN_NB, 1024>>>(cnt, bsum, offs, cur, dinv);
    csr_scatter_kernel<<<NB_ET, 256>>>(ei, cur, csr);

    for (int l = 0; l < 3; l++) {
        // --- GCN: GEMM -> gather(+bias+relu) ---
        mm_tf32_k128<false><<<NB_GEMM, 256>>>(l == 0 ? x : buf0, wprep, l * 2,
                                              nullptr, buf1, NNODES);
        gcn_gather_kernel<<<NB_WARP, 256>>>(buf1, offs, csr, dinv, bg[l], buf0);

        // --- GAT: GEMM(+bias) -> fused online-softmax gather ---
        mm_tf32_k128<true><<<NB_GEMM, 256>>>(buf0, wprep, l * 2 + 1,
                                             ba[l], buf1, NNODES);
        gat_gather_kernel<<<NB_WARP, 256>>>(buf1, offs, csr, buf0);
    }

    // Global mean pool (concat halves identical)
    cudaMemsetAsync(acc, 0, HDIM * sizeof(float), 0);
    colsum_kernel<<<NB_COL, 128>>>(buf0, acc);
    writeout_kernel<<<1, 256>>>(acc, (float*)d_out);
}

// round 6
// speedup vs baseline: 1.4327x; 1.0207x over previous
#include <cuda_runtime.h>
#include <cuda_fp16.h>
#include <math.h>
#include <stdint.h>

// Problem constants
#define NNODES 40000
#define NEDGES 640000
#define ETOT   (NEDGES + NNODES)   // edges + appended self loops
#define HDIM   128
#define SCAN_NB 40                 // ceil(NNODES / 1024)

// ---------------------------------------------------------------------------
// Scratch (device globals; no allocation allowed in kernel_launch)
// ---------------------------------------------------------------------------
__device__ __align__(16) __half g_h0[(size_t)NNODES * HDIM];  // 10.25 MB
__device__ __align__(16) __half g_h1[(size_t)NNODES * HDIM];  // 10.25 MB
__device__ int   g_csr[ETOT];            // packed: col | (invalid << 31)
__device__ int   g_cnt[NNODES];          // edge count per row (excl. self loop)
__device__ int   g_offs[NNODES + 1];
__device__ int   g_cur[NNODES];
__device__ int   g_bsum[64];
__device__ float g_dinv[NNODES];
__device__ float g_acc[HDIM];
__device__ float g_wprep[6 * 128 * 32 * 4];  // 6 tf32-interleaved Weff, 393KB
__device__ int   g_is64;

// ---------------------------------------------------------------------------
// fp16 helpers: load/store 4 features (8 B) per lane
// ---------------------------------------------------------------------------
__device__ __forceinline__ float4 ldh4(const __half* p) {
    uint2 u = *(const uint2*)p;
    float2 f0 = __half22float2(*(__half2*)&u.x);
    float2 f1 = __half22float2(*(__half2*)&u.y);
    return make_float4(f0.x, f0.y, f1.x, f1.y);
}
__device__ __forceinline__ void sth4(__half* p, float4 v) {
    uint2 u;
    *(__half2*)&u.x = __floats2half2_rn(v.x, v.y);
    *(__half2*)&u.y = __floats2half2_rn(v.z, v.w);
    *(uint2*)p = u;
}

// ---------------------------------------------------------------------------
// Edge-index dtype detection: logically int64 [2,E] but may be int32
// physically (JAX x64 off). int32 data read as int64 packs two indices ->
// almost surely out of [0, NNODES) somewhere in the first 1024 slots.
// ---------------------------------------------------------------------------
__global__ void detect_dtype_kernel(const void* ei) {
    __shared__ int ok;
    if (threadIdx.x == 0) ok = 1;
    __syncthreads();
    const long long* p = (const long long*)ei;
    for (int i = threadIdx.x; i < 1024; i += blockDim.x) {
        long long v = p[i];
        if (v < 0 || v >= NNODES) atomicAnd(&ok, 0);
    }
    __syncthreads();
    if (threadIdx.x == 0) g_is64 = ok;
}

// ---------------------------------------------------------------------------
// CSR build
// ---------------------------------------------------------------------------
__global__ void cnt_acc_kernel(const void* ei, int* cnt) {
    int e = blockIdx.x * blockDim.x + threadIdx.x;
    if (e >= NEDGES) return;
    int r = g_is64 ? (int)((const long long*)ei)[e] : ((const int*)ei)[e];
    atomicAdd(&cnt[r], 1);
}

// Phase 1: per-block (1024 elems) exclusive scan of deg = cnt+1; block totals.
__global__ __launch_bounds__(1024) void scan1_kernel(
    const int* __restrict__ cnt, int* __restrict__ excl, int* __restrict__ bsum)
{
    __shared__ int wsum[32];
    int t = threadIdx.x;
    int i = blockIdx.x * 1024 + t;
    int lane = t & 31, w = t >> 5;
    int v = (i < NNODES) ? (cnt[i] + 1) : 0;    // +1 = appended self loop
    int s = v;
#pragma unroll
    for (int d = 1; d < 32; d <<= 1) {
        int u = __shfl_up_sync(0xffffffffu, s, d);
        if (lane >= d) s += u;
    }
    if (lane == 31) wsum[w] = s;
    __syncthreads();
    if (w == 0) {
        int ws = wsum[lane];
#pragma unroll
        for (int d = 1; d < 32; d <<= 1) {
            int u = __shfl_up_sync(0xffffffffu, ws, d);
            if (lane >= d) ws += u;
        }
        wsum[lane] = ws;
    }
    __syncthreads();
    int incl = s + (w ? wsum[w - 1] : 0);
    if (i < NNODES) excl[i] = incl - v;          // exclusive within block
    if (t == 0) bsum[blockIdx.x] = wsum[31];     // block total
}

// Phase 2: exclusive scan of SCAN_NB block totals (single block).
__global__ void scan2_kernel(int* bsum) {
    __shared__ int sm[SCAN_NB];
    int t = threadIdx.x;
    if (t < SCAN_NB) sm[t] = bsum[t];
    __syncthreads();
    if (t == 0) {
        int run = 0;
        for (int b = 0; b < SCAN_NB; b++) {
            int v = sm[b];
            sm[b] = run;
            run += v;
        }
    }
    __syncthreads();
    if (t < SCAN_NB) bsum[t] = sm[t];
}

// Phase 3: finalize offsets, write cur and dinv.
__global__ __launch_bounds__(1024) void scan3_kernel(
    const int* __restrict__ cnt, const int* __restrict__ bsum,
    int* __restrict__ offs, int* __restrict__ cur, float* __restrict__ dinv)
{
    int i = blockIdx.x * 1024 + threadIdx.x;
    if (i < NNODES) {
        int off = offs[i] + bsum[blockIdx.x];    // offs held within-block excl
        offs[i] = off;
        cur[i]  = off;
        dinv[i] = rsqrtf((float)(cnt[i] + 1));
    }
    if (i == 0) offs[NNODES] = ETOT;
}

__global__ void csr_scatter_kernel(const void* ei, int* cur, int* csr) {
    int e = blockIdx.x * blockDim.x + threadIdx.x;
    if (e >= ETOT) return;
    int r, c, invalid = 0;
    if (e < NEDGES) {
        if (g_is64) {
            const long long* p = (const long long*)ei;
            r = (int)p[e]; c = (int)p[NEDGES + e];
        } else {
            const int* p = (const int*)ei;
            r = p[e]; c = p[NEDGES + e];
        }
        if (r == c) invalid = (int)0x80000000;  // masked for GAT, kept for GCN
    } else {
        r = c = e - NEDGES;
    }
    int pos = atomicAdd(&cur[r], 1);
    csr[pos] = c | invalid;
}

// ---------------------------------------------------------------------------
// Weight prep: all 6 effective weights -> tf32, kpos8-interleaved, once.
// Layout: g_wprep[((mat*4 + ck)*128 + n)*32 + kpos8(k&31)].
// mats: 0=Wg0, 1=Wa0, 2=Wg1(+fold), 3=Wa1, 4=Wg2(+fold), 5=Wa2
// ---------------------------------------------------------------------------
__device__ __forceinline__ uint32_t f2tf32(float v) {
    uint32_t r;
    asm("cvt.rna.tf32.f32 %0, %1;" : "=r"(r) : "f"(v));
    return r;
}
__device__ __forceinline__ int kpos8(int k) {   // k in [0,32)
    return (k >> 3) * 8 + (k & 3) * 2 + ((k >> 2) & 1);
}

__global__ void wprep_kernel(const float* Wg0, const float* Wa0,
                             const float* Wg1, const float* Wa1,
                             const float* Wg2, const float* Wa2,
                             float* out)
{
    int m = blockIdx.x;
    const float* W; bool add;
    switch (m) {
        case 0: W = Wg0; add = false; break;
        case 1: W = Wa0; add = false; break;
        case 2: W = Wg1; add = true;  break;
        case 3: W = Wa1; add = false; break;
        case 4: W = Wg2; add = true;  break;
        default: W = Wa2; add = false; break;
    }
    for (int i = threadIdx.x; i < 128 * 128; i += blockDim.x) {
        int n = i & 127, k = i >> 7;
        float v = W[(size_t)k * 128 + n];
        if (add) v += W[(size_t)(k + 128) * 128 + n];
        int ck = k >> 5, kp = kpos8(k & 31);
        out[(((size_t)(m * 4 + ck) * 128 + n) * 32) + kp] = __uint_as_float(f2tf32(v));
    }
}

// ---------------------------------------------------------------------------
// tf32 tensor-core GEMM: C[M,128] = A[M,128] @ Weff[128,128] (+bias).
// 256 threads (8 warps, 2 along M x 4 along N), warp tile 64x32.
// A is fp32 (layer 0) or fp16 (fp16 widens EXACTLY into tf32 -> no cvt).
// C written as fp16. W staged from pre-interleaved g_wprep.
// ---------------------------------------------------------------------------
#define KS_STRIDE 40

__device__ __forceinline__ void mma_tf32(float4& c, uint32_t a0, uint32_t a1,
                                         uint32_t a2, uint32_t a3,
                                         uint32_t b0, uint32_t b1) {
    asm volatile(
        "mma.sync.aligned.m16n8k8.row.col.f32.tf32.tf32.f32 "
        "{%0,%1,%2,%3}, {%4,%5,%6,%7}, {%8,%9}, {%0,%1,%2,%3};"
        : "+f"(c.x), "+f"(c.y), "+f"(c.z), "+f"(c.w)
        : "r"(a0), "r"(a1), "r"(a2), "r"(a3), "r"(b0), "r"(b1));
}

template<bool AHALF, bool BIAS>
__global__ __launch_bounds__(256) void mm_tf32_k128(
    const void* __restrict__ Av, const float* __restrict__ wprep, int mat,
    const float* __restrict__ bias, __half* __restrict__ C, int M)
{
    __shared__ float Wp[128 * KS_STRIDE];   // [n=128][kpos 0..31]
    __shared__ float Ap[128 * KS_STRIDE];   // [m=128][kpos 0..31]

    const int t    = threadIdx.x;
    const int warp = t >> 5;
    const int lane = t & 31;
    const int gid  = lane >> 2;             // 0..7
    const int tg   = lane & 3;              // 0..3
    const int wm   = warp & 1;              // 2 warps along M (64 rows each)
    const int wn   = warp >> 1;             // 4 warps along N (32 cols each)
    const int m0   = blockIdx.x * 128;

    float4 c[4][4];
#pragma unroll
    for (int i = 0; i < 4; i++)
#pragma unroll
        for (int j = 0; j < 4; j++) c[i][j] = make_float4(0.f, 0.f, 0.f, 0.f);

    for (int ck = 0; ck < 4; ck++) {
        __syncthreads();
        // Stage W chunk: pre-interleaved, pure float4 copies (4 iters)
        const float* wsrc = wprep + ((size_t)(mat * 4 + ck) * 128) * 32;
        for (int i = t; i < 1024; i += 256) {
            int n   = i >> 3;
            int kp4 = (i & 7) << 2;
            *(float4*)&Wp[(size_t)n * KS_STRIDE + kp4] =
                *(const float4*)&wsrc[(size_t)n * 32 + kp4];
        }
        // Stage A chunk: 128 rows x 32 k (4 iters)
        for (int i = t; i < 1024; i += 256) {
            int m  = i >> 3;
            int k4 = (i & 7) << 2;
            float* ap = &Ap[(size_t)m * KS_STRIDE];
            if (AHALF) {
                float4 v = make_float4(0.f, 0.f, 0.f, 0.f);
                if (m0 + m < M)
                    v = ldh4((const __half*)Av + (size_t)(m0 + m) * 128 + ck * 32 + k4);
                // fp16 values are exact tf32 operands: no rounding needed
                ap[kpos8(k4 + 0)] = v.x;
                ap[kpos8(k4 + 1)] = v.y;
                ap[kpos8(k4 + 2)] = v.z;
                ap[kpos8(k4 + 3)] = v.w;
            } else {
                float4 v = make_float4(0.f, 0.f, 0.f, 0.f);
                if (m0 + m < M)
                    v = *(const float4*)((const float*)Av + (size_t)(m0 + m) * 128 + ck * 32 + k4);
                ap[kpos8(k4 + 0)] = __uint_as_float(f2tf32(v.x));
                ap[kpos8(k4 + 1)] = __uint_as_float(f2tf32(v.y));
                ap[kpos8(k4 + 2)] = __uint_as_float(f2tf32(v.z));
                ap[kpos8(k4 + 3)] = __uint_as_float(f2tf32(v.w));
            }
        }
        __syncthreads();

#pragma unroll
        for (int ks = 0; ks < 4; ks++) {
            const int kb = ks * 8 + tg * 2;
            uint32_t b0[4], b1[4];
#pragma unroll
            for (int nt = 0; nt < 4; nt++) {
                int col = wn * 32 + nt * 8 + gid;
                float2 b = *(const float2*)&Wp[(size_t)col * KS_STRIDE + kb];
                b0[nt] = __float_as_uint(b.x);
                b1[nt] = __float_as_uint(b.y);
            }
#pragma unroll
            for (int mt = 0; mt < 4; mt++) {
                int row = wm * 64 + mt * 16 + gid;
                float2 a02 = *(const float2*)&Ap[(size_t)row * KS_STRIDE + kb];
                float2 a13 = *(const float2*)&Ap[(size_t)(row + 8) * KS_STRIDE + kb];
                uint32_t a0 = __float_as_uint(a02.x);
                uint32_t a2 = __float_as_uint(a02.y);
                uint32_t a1 = __float_as_uint(a13.x);
                uint32_t a3 = __float_as_uint(a13.y);
#pragma unroll
                for (int nt = 0; nt < 4; nt++)
                    mma_tf32(c[mt][nt], a0, a1, a2, a3, b0[nt], b1[nt]);
            }
        }
    }

    // Epilogue: fp16 output. c.x,c.y -> (r0,col..col+1); c.z,c.w -> (r0+8,...)
#pragma unroll
    for (int mt = 0; mt < 4; mt++) {
        int r0 = m0 + wm * 64 + mt * 16 + gid;
#pragma unroll
        for (int nt = 0; nt < 4; nt++) {
            int col = wn * 32 + nt * 8 + tg * 2;
            float bx = 0.f, by = 0.f;
            if (BIAS) { bx = __ldg(&bias[col]); by = __ldg(&bias[col + 1]); }
            if (r0 < M) {
                *(__half2*)&C[(size_t)r0 * 128 + col] =
                    __floats2half2_rn(c[mt][nt].x + bx, c[mt][nt].y + by);
            }
            if (r0 + 8 < M) {
                *(__half2*)&C[(size_t)(r0 + 8) * 128 + col] =
                    __floats2half2_rn(c[mt][nt].z + bx, c[mt][nt].w + by);
            }
        }
    }
}

// ---------------------------------------------------------------------------
// GCN gather (warp per destination), unroll-4, fused bias + relu. fp16 io.
// ---------------------------------------------------------------------------
__global__ __launch_bounds__(256) void gcn_gather_kernel(
    const __half* __restrict__ xw, const int* __restrict__ offs,
    const int* __restrict__ csr, const float* __restrict__ dinv,
    const float* __restrict__ bias, __half* __restrict__ out)
{
    int node = (blockIdx.x * 256 + threadIdx.x) >> 5;
    int lane = threadIdx.x & 31;
    if (node >= NNODES) return;
    int s = __ldg(&offs[node]);
    int e = __ldg(&offs[node + 1]);
    float dr = __ldg(&dinv[node]);

    float4 A0 = make_float4(0.f,0.f,0.f,0.f), A1 = A0, A2 = A0, A3 = A0;
    int p = s;
    for (; p + 4 <= e; p += 4) {
        int c0 = __ldg(&csr[p + 0]) & 0x7fffffff;
        int c1 = __ldg(&csr[p + 1]) & 0x7fffffff;
        int c2 = __ldg(&csr[p + 2]) & 0x7fffffff;
        int c3 = __ldg(&csr[p + 3]) & 0x7fffffff;
        float n0 = dr * __ldg(&dinv[c0]);
        float n1 = dr * __ldg(&dinv[c1]);
        float n2 = dr * __ldg(&dinv[c2]);
        float n3 = dr * __ldg(&dinv[c3]);
        float4 v0 = ldh4(xw + (size_t)c0 * 128 + lane * 4);
        float4 v1 = ldh4(xw + (size_t)c1 * 128 + lane * 4);
        float4 v2 = ldh4(xw + (size_t)c2 * 128 + lane * 4);
        float4 v3 = ldh4(xw + (size_t)c3 * 128 + lane * 4);
        A0.x = fmaf(v0.x,n0,A0.x); A0.y = fmaf(v0.y,n0,A0.y); A0.z = fmaf(v0.z,n0,A0.z); A0.w = fmaf(v0.w,n0,A0.w);
        A1.x = fmaf(v1.x,n1,A1.x); A1.y = fmaf(v1.y,n1,A1.y); A1.z = fmaf(v1.z,n1,A1.z); A1.w = fmaf(v1.w,n1,A1.w);
        A2.x = fmaf(v2.x,n2,A2.x); A2.y = fmaf(v2.y,n2,A2.y); A2.z = fmaf(v2.z,n2,A2.z); A2.w = fmaf(v2.w,n2,A2.w);
        A3.x = fmaf(v3.x,n3,A3.x); A3.y = fmaf(v3.y,n3,A3.y); A3.z = fmaf(v3.z,n3,A3.z); A3.w = fmaf(v3.w,n3,A3.w);
    }
    for (; p < e; p++) {
        int c0 = __ldg(&csr[p]) & 0x7fffffff;
        float n0 = dr * __ldg(&dinv[c0]);
        float4 v0 = ldh4(xw + (size_t)c0 * 128 + lane * 4);
        A0.x = fmaf(v0.x,n0,A0.x); A0.y = fmaf(v0.y,n0,A0.y); A0.z = fmaf(v0.z,n0,A0.z); A0.w = fmaf(v0.w,n0,A0.w);
    }
    float4 acc;
    acc.x = (A0.x + A1.x) + (A2.x + A3.x);
    acc.y = (A0.y + A1.y) + (A2.y + A3.y);
    acc.z = (A0.z + A1.z) + (A2.z + A3.z);
    acc.w = (A0.w + A1.w) + (A2.w + A3.w);
    float4 b = *(const float4*)&bias[lane * 4];
    acc.x = fmaxf(acc.x + b.x, 0.0f);
    acc.y = fmaxf(acc.y + b.y, 0.0f);
    acc.z = fmaxf(acc.z + b.z, 0.0f);
    acc.w = fmaxf(acc.w + b.w, 0.0f);
    sth4(out + (size_t)node * 128 + lane * 4, acc);
}

// ---------------------------------------------------------------------------
// GAT gather: warp per destination, TWO interleaved online-softmax states.
// fp16 io, fp32 math.
// ---------------------------------------------------------------------------
__device__ __forceinline__ float warp_dot(float4 a, float4 b) {
    float d = a.x*b.x + a.y*b.y + a.z*b.z + a.w*b.w;
#pragma unroll
    for (int s = 16; s; s >>= 1) d += __shfl_xor_sync(0xffffffffu, d, s);
    return d;
}

__global__ __launch_bounds__(256) void gat_gather_kernel(
    const __half* __restrict__ h, const int* __restrict__ offs,
    const int* __restrict__ csr, __half* __restrict__ out)
{
    int node = (blockIdx.x * 256 + threadIdx.x) >> 5;
    int lane = threadIdx.x & 31;
    if (node >= NNODES) return;
    int s = __ldg(&offs[node]);
    int e = __ldg(&offs[node + 1]);

    float4 hr = ldh4(h + (size_t)node * 128 + lane * 4);

    float m0 = -INFINITY, d0 = 0.0f;
    float m1 = -INFINITY, d1 = 0.0f;
    float4 a0 = make_float4(0.f,0.f,0.f,0.f), a1 = a0;

    int p = s;
    for (; p + 2 <= e; p += 2) {
        int r0 = __ldg(&csr[p]);
        int r1 = __ldg(&csr[p + 1]);
        float4 h0 = ldh4(h + (size_t)(r0 & 0x7fffffff) * 128 + lane * 4);
        float4 h1 = ldh4(h + (size_t)(r1 & 0x7fffffff) * 128 + lane * 4);
        float t0 = h0.x*hr.x + h0.y*hr.y + h0.z*hr.z + h0.w*hr.w;
        float t1 = h1.x*hr.x + h1.y*hr.y + h1.z*hr.z + h1.w*hr.w;
#pragma unroll
        for (int sh = 16; sh; sh >>= 1) {
            t0 += __shfl_xor_sync(0xffffffffu, t0, sh);
            t1 += __shfl_xor_sync(0xffffffffu, t1, sh);
        }
        if (r0 >= 0) {
            float al = (t0 >= 0.f) ? t0 : 0.2f * t0;
            if (al > m0) {
                float sc = __expf(m0 - al);
                d0 *= sc; a0.x *= sc; a0.y *= sc; a0.z *= sc; a0.w *= sc;
                m0 = al;
            }
            float w = __expf(al - m0);
            d0 += w;
            a0.x = fmaf(h0.x,w,a0.x); a0.y = fmaf(h0.y,w,a0.y);
            a0.z = fmaf(h0.z,w,a0.z); a0.w = fmaf(h0.w,w,a0.w);
        }
        if (r1 >= 0) {
            float al = (t1 >= 0.f) ? t1 : 0.2f * t1;
            if (al > m1) {
                float sc = __expf(m1 - al);
                d1 *= sc; a1.x *= sc; a1.y *= sc; a1.z *= sc; a1.w *= sc;
                m1 = al;
            }
            float w = __expf(al - m1);
            d1 += w;
            a1.x = fmaf(h1.x,w,a1.x); a1.y = fmaf(h1.y,w,a1.y);
            a1.z = fmaf(h1.z,w,a1.z); a1.w = fmaf(h1.w,w,a1.w);
        }
    }
    if (p < e) {
        int r0 = __ldg(&csr[p]);
        float4 h0 = ldh4(h + (size_t)(r0 & 0x7fffffff) * 128 + lane * 4);
        float t0 = warp_dot(hr, h0);
        if (r0 >= 0) {
            float al = (t0 >= 0.f) ? t0 : 0.2f * t0;
            if (al > m0) {
                float sc = __expf(m0 - al);
                d0 *= sc; a0.x *= sc; a0.y *= sc; a0.z *= sc; a0.w *= sc;
                m0 = al;
            }
            float w = __expf(al - m0);
            d0 += w;
            a0.x = fmaf(h0.x,w,a0.x); a0.y = fmaf(h0.y,w,a0.y);
            a0.z = fmaf(h0.z,w,a0.z); a0.w = fmaf(h0.w,w,a0.w);
        }
    }

    float M_ = fmaxf(m0, m1);
    float s0 = __expf(m0 - M_);
    float s1 = __expf(m1 - M_);
    float den = d0 * s0 + d1 * s1;
    float4 acc;
    acc.x = a0.x * s0 + a1.x * s1;
    acc.y = a0.y * s0 + a1.y * s1;
    acc.z = a0.z * s0 + a1.z * s1;
    acc.w = a0.w * s0 + a1.w * s1;
    float inv = 1.0f / fmaxf(den, 1e-16f);
    acc.x *= inv; acc.y *= inv; acc.z *= inv; acc.w *= inv;
    sth4(out + (size_t)node * 128 + lane * 4, acc);
}

// ---------------------------------------------------------------------------
// Global mean pool (fp16 in, fp32 accum)
// ---------------------------------------------------------------------------
__global__ void colsum_kernel(const __half* __restrict__ h, float* __restrict__ acc)
{
    int col = threadIdx.x;                 // 128 threads
    int r0   = blockIdx.x * 256;
    int rend = r0 + 256;
    if (rend > NNODES) rend = NNODES;
    float s = 0.0f;
    for (int r = r0; r < rend; r++) s += __half2float(h[(size_t)r * 128 + col]);
    atomicAdd(&acc[col], s);
}

__global__ void writeout_kernel(const float* __restrict__ acc, float* __restrict__ out)
{
    int i = threadIdx.x;                   // 256 threads
    out[i] = acc[i & 127] * (1.0f / (float)NNODES);
}

// ---------------------------------------------------------------------------
// Launch
// ---------------------------------------------------------------------------
extern "C" void kernel_launch(void* const* d_in, const int* in_sizes, int n_in,
                              void* d_out, int out_size)
{
    const float* x  = (const float*)d_in[0];
    const void*  ei = d_in[1];
    const float* Wg[3] = {(const float*)d_in[2], (const float*)d_in[6],  (const float*)d_in[10]};
    const float* bg[3] = {(const float*)d_in[3], (const float*)d_in[7],  (const float*)d_in[11]};
    const float* Wa[3] = {(const float*)d_in[4], (const float*)d_in[8],  (const float*)d_in[12]};
    const float* ba[3] = {(const float*)d_in[5], (const float*)d_in[9],  (const float*)d_in[13]};

    __half *h0, *h1;
    float *dinv, *acc, *wprep;
    int *csr, *cnt, *offs, *cur, *bsum;
    cudaGetSymbolAddress((void**)&h0,   g_h0);
    cudaGetSymbolAddress((void**)&h1,   g_h1);
    cudaGetSymbolAddress((void**)&dinv, g_dinv);
    cudaGetSymbolAddress((void**)&acc,  g_acc);
    cudaGetSymbolAddress((void**)&wprep,g_wprep);
    cudaGetSymbolAddress((void**)&csr,  g_csr);
    cudaGetSymbolAddress((void**)&cnt,  g_cnt);
    cudaGetSymbolAddress((void**)&offs, g_offs);
    cudaGetSymbolAddress((void**)&cur,  g_cur);
    cudaGetSymbolAddress((void**)&bsum, g_bsum);

    const int NB_E    = (NEDGES + 255) / 256;
    const int NB_ET   = (ETOT + 255) / 256;
    const int NB_WARP = (NNODES + 7) / 8;        // warp-per-node, 8 warps/block
    const int NB_GEMM = (NNODES + 127) / 128;    // 313
    const int NB_COL  = (NNODES + 255) / 256;

    // Weight prep (independent of everything else)
    wprep_kernel<<<6, 256>>>(Wg[0], Wa[0], Wg[1], Wa[1], Wg[2], Wa[2], wprep);

    // CSR build (parallel scan)
    detect_dtype_kernel<<<1, 256>>>(ei);
    cudaMemsetAsync(cnt, 0, NNODES * sizeof(int), 0);
    cnt_acc_kernel<<<NB_E, 256>>>(ei, cnt);
    scan1_kernel<<<SCAN_NB, 1024>>>(cnt, offs, bsum);
    scan2_kernel<<<1, 64>>>(bsum);
    scan3_kernel<<<SCAN_NB, 1024>>>(cnt, bsum, offs, cur, dinv);
    csr_scatter_kernel<<<NB_ET, 256>>>(ei, cur, csr);

    for (int l = 0; l < 3; l++) {
        // --- GCN: GEMM -> gather(+bias+relu) ---   (A: x fp32 | h1 fp16)
        if (l == 0)
            mm_tf32_k128<false, false><<<NB_GEMM, 256>>>(x,  wprep, 0,     nullptr, h0, NNODES);
        else
            mm_tf32_k128<true,  false><<<NB_GEMM, 256>>>(h1, wprep, l * 2, nullptr, h0, NNODES);
        gcn_gather_kernel<<<NB_WARP, 256>>>(h0, offs, csr, dinv, bg[l], h1);

        // --- GAT: GEMM(+bias) -> fused online-softmax gather ---
        mm_tf32_k128<true, true><<<NB_GEMM, 256>>>(h1, wprep, l * 2 + 1, ba[l], h0, NNODES);
        gat_gather_kernel<<<NB_WARP, 256>>>(h0, offs, csr, h1);
    }

    // Global mean pool (concat halves identical); h1 holds final features
    cudaMemsetAsync(acc, 0, HDIM * sizeof(float), 0);
    colsum_kernel<<<NB_COL, 128>>>(h1, acc);
    writeout_kernel<<<1, 256>>>(acc, (float*)d_out);
}

// round 8
// speedup vs baseline: 1.6714x; 1.1667x over previous
#include <cuda_runtime.h>
#include <cuda_fp16.h>
#include <math.h>
#include <stdint.h>

// Problem constants
#define NNODES 40000
#define NEDGES 640000
#define ETOT   (NEDGES + NNODES)   // edges + appended self loops
#define HDIM   128
#define SCAN_NB 40                 // ceil(NNODES / 1024)
#define COL_NB  128                // colsum grid
#define COL_CHUNK 313              // ceil(NNODES / COL_NB)

// ---------------------------------------------------------------------------
// Scratch (device globals; no allocation allowed in kernel_launch)
// ---------------------------------------------------------------------------
__device__ __align__(16) __half g_h0[(size_t)NNODES * HDIM];  // 10.25 MB
__device__ __align__(16) __half g_h1[(size_t)NNODES * HDIM];  // 10.25 MB
__device__ int   g_csr[ETOT];            // packed: col | (invalid << 31)
__device__ int   g_cnt[NNODES];          // edge count per row (excl. self loop)
__device__ int   g_offs[NNODES + 1];
__device__ int   g_cur[NNODES];
__device__ int   g_bsum[64];
__device__ float g_dinv[NNODES];
__device__ float g_acc[HDIM];
__device__ int   g_ctr;                  // colsum completion counter
__device__ float g_wprep[6 * 128 * 32 * 4];  // 6 tf32-interleaved Weff, 393KB
__device__ int   g_is64;

// ---------------------------------------------------------------------------
// fp16 helpers: 8 features (16 B) per lane
// ---------------------------------------------------------------------------
struct F8 { float v[8]; };
__device__ __forceinline__ F8 ldh8(const __half* p) {
    uint4 u = *(const uint4*)p;
    F8 r; float2 f;
    f = __half22float2(*(__half2*)&u.x); r.v[0] = f.x; r.v[1] = f.y;
    f = __half22float2(*(__half2*)&u.y); r.v[2] = f.x; r.v[3] = f.y;
    f = __half22float2(*(__half2*)&u.z); r.v[4] = f.x; r.v[5] = f.y;
    f = __half22float2(*(__half2*)&u.w); r.v[6] = f.x; r.v[7] = f.y;
    return r;
}
__device__ __forceinline__ void sth8(__half* p, const float* v) {
    uint4 u;
    *(__half2*)&u.x = __floats2half2_rn(v[0], v[1]);
    *(__half2*)&u.y = __floats2half2_rn(v[2], v[3]);
    *(__half2*)&u.z = __floats2half2_rn(v[4], v[5]);
    *(__half2*)&u.w = __floats2half2_rn(v[6], v[7]);
    *(uint4*)p = u;
}

// ---------------------------------------------------------------------------
// detect dtype (block 0) + zero cnt (all blocks). edge_index is logically
// int64 [2,E] but may be int32 physically (JAX x64 off).
// ---------------------------------------------------------------------------
__global__ __launch_bounds__(1024) void detect_zero_kernel(const void* ei, int* cnt) {
    int i = blockIdx.x * 1024 + threadIdx.x;
    if (i < NNODES) cnt[i] = 0;
    if (blockIdx.x == 0) {
        __shared__ int ok;
        if (threadIdx.x == 0) ok = 1;
        __syncthreads();
        const long long* p = (const long long*)ei;
        long long v = p[threadIdx.x];      // 1024 samples
        if (v < 0 || v >= NNODES) atomicAnd(&ok, 0);
        __syncthreads();
        if (threadIdx.x == 0) g_is64 = ok;
    }
}

__global__ void cnt_acc_kernel(const void* ei, int* cnt) {
    int e = blockIdx.x * blockDim.x + threadIdx.x;
    if (e >= NEDGES) return;
    int r = g_is64 ? (int)((const long long*)ei)[e] : ((const int*)ei)[e];
    atomicAdd(&cnt[r], 1);
}

// Phase 1: per-block (1024) exclusive scan of deg = cnt+1; block totals.
// Block 0 also zeroes g_acc for the final pool.
__global__ __launch_bounds__(1024) void scan1_kernel(
    const int* __restrict__ cnt, int* __restrict__ excl, int* __restrict__ bsum,
    float* __restrict__ acc)
{
    __shared__ int wsum[32];
    int t = threadIdx.x;
    int i = blockIdx.x * 1024 + t;
    int lane = t & 31, w = t >> 5;
    if (blockIdx.x == 0 && t < HDIM) acc[t] = 0.0f;
    int v = (i < NNODES) ? (cnt[i] + 1) : 0;    // +1 = appended self loop
    int s = v;
#pragma unroll
    for (int d = 1; d < 32; d <<= 1) {
        int u = __shfl_up_sync(0xffffffffu, s, d);
        if (lane >= d) s += u;
    }
    if (lane == 31) wsum[w] = s;
    __syncthreads();
    if (w == 0) {
        int ws = wsum[lane];
#pragma unroll
        for (int d = 1; d < 32; d <<= 1) {
            int u = __shfl_up_sync(0xffffffffu, ws, d);
            if (lane >= d) ws += u;
        }
        wsum[lane] = ws;
    }
    __syncthreads();
    int incl = s + (w ? wsum[w - 1] : 0);
    if (i < NNODES) excl[i] = incl - v;
    if (t == 0) bsum[blockIdx.x] = wsum[31];
}

// Phase 2+3 merged: each block prefix-sums bsum locally, finalizes offsets.
__global__ __launch_bounds__(1024) void scan3_kernel(
    const int* __restrict__ cnt, const int* __restrict__ bsum,
    int* __restrict__ offs, int* __restrict__ cur, float* __restrict__ dinv)
{
    __shared__ int base;
    if (threadIdx.x == 0) {
        int run = 0;
        for (int b = 0; b < (int)blockIdx.x; b++) run += bsum[b];
        base = run;
    }
    __syncthreads();
    int i = blockIdx.x * 1024 + threadIdx.x;
    if (i < NNODES) {
        int off = offs[i] + base;
        offs[i] = off;
        cur[i]  = off;
        dinv[i] = rsqrtf((float)(cnt[i] + 1));
    }
    if (i == 0) offs[NNODES] = ETOT;
}

__global__ void csr_scatter_kernel(const void* ei, int* cur, int* csr) {
    int e = blockIdx.x * blockDim.x + threadIdx.x;
    if (e >= ETOT) return;
    int r, c, invalid = 0;
    if (e < NEDGES) {
        if (g_is64) {
            const long long* p = (const long long*)ei;
            r = (int)p[e]; c = (int)p[NEDGES + e];
        } else {
            const int* p = (const int*)ei;
            r = p[e]; c = p[NEDGES + e];
        }
        if (r == c) invalid = (int)0x80000000;  // masked for GAT, kept for GCN
    } else {
        r = c = e - NEDGES;
    }
    int pos = atomicAdd(&cur[r], 1);
    csr[pos] = c | invalid;
}

// ---------------------------------------------------------------------------
// Weight prep: all 6 effective weights -> tf32, kpos8-interleaved, once.
// g_wprep[((mat*4 + ck)*128 + n)*32 + kpos8(k&31)].
// mats: 0=Wg0, 1=Wa0, 2=Wg1(+fold), 3=Wa1, 4=Wg2(+fold), 5=Wa2
// ---------------------------------------------------------------------------
__device__ __forceinline__ uint32_t f2tf32(float v) {
    uint32_t r;
    asm("cvt.rna.tf32.f32 %0, %1;" : "=r"(r) : "f"(v));
    return r;
}
__device__ __forceinline__ int kpos8(int k) {   // k in [0,32)
    return (k >> 3) * 8 + (k & 3) * 2 + ((k >> 2) & 1);
}

__global__ void wprep_kernel(const float* Wg0, const float* Wa0,
                             const float* Wg1, const float* Wa1,
                             const float* Wg2, const float* Wa2,
                             float* out)
{
    int m = blockIdx.x;
    const float* W; bool add;
    switch (m) {
        case 0: W = Wg0; add = false; break;
        case 1: W = Wa0; add = false; break;
        case 2: W = Wg1; add = true;  break;
        case 3: W = Wa1; add = false; break;
        case 4: W = Wg2; add = true;  break;
        default: W = Wa2; add = false; break;
    }
    for (int i = threadIdx.x; i < 128 * 128; i += blockDim.x) {
        int n = i & 127, k = i >> 7;
        float v = W[(size_t)k * 128 + n];
        if (add) v += W[(size_t)(k + 128) * 128 + n];
        int ck = k >> 5, kp = kpos8(k & 31);
        out[(((size_t)(m * 4 + ck) * 128 + n) * 32) + kp] = __uint_as_float(f2tf32(v));
    }
}

// ---------------------------------------------------------------------------
// tf32 tensor-core GEMM: C[M,128] = A[M,128] @ Weff[128,128] (+bias).
// 256 threads (8 warps, 2 along M x 4 along N), warp tile 64x32.
// A staged via 16B loads of 8 consecutive k + paired STS.64 of (k,k+4):
// conflict-free. fp16 A widens exactly into tf32.
// ---------------------------------------------------------------------------
#define KS_STRIDE 40

__device__ __forceinline__ void mma_tf32(float4& c, uint32_t a0, uint32_t a1,
                                         uint32_t a2, uint32_t a3,
                                         uint32_t b0, uint32_t b1) {
    asm volatile(
        "mma.sync.aligned.m16n8k8.row.col.f32.tf32.tf32.f32 "
        "{%0,%1,%2,%3}, {%4,%5,%6,%7}, {%8,%9}, {%0,%1,%2,%3};"
        : "+f"(c.x), "+f"(c.y), "+f"(c.z), "+f"(c.w)
        : "r"(a0), "r"(a1), "r"(a2), "r"(a3), "r"(b0), "r"(b1));
}

template<bool AHALF, bool BIAS>
__global__ __launch_bounds__(256) void mm_tf32_k128(
    const void* __restrict__ Av, const float* __restrict__ wprep, int mat,
    const float* __restrict__ bias, __half* __restrict__ C, int M)
{
    __shared__ float Wp[128 * KS_STRIDE];   // [n=128][kpos 0..31]
    __shared__ float Ap[128 * KS_STRIDE];   // [m=128][kpos 0..31]

    const int t    = threadIdx.x;
    const int warp = t >> 5;
    const int lane = t & 31;
    const int gid  = lane >> 2;             // 0..7
    const int tg   = lane & 3;              // 0..3
    const int wm   = warp & 1;              // 2 warps along M (64 rows each)
    const int wn   = warp >> 1;             // 4 warps along N (32 cols each)
    const int m0   = blockIdx.x * 128;

    float4 c[4][4];
#pragma unroll
    for (int i = 0; i < 4; i++)
#pragma unroll
        for (int j = 0; j < 4; j++) c[i][j] = make_float4(0.f, 0.f, 0.f, 0.f);

    for (int ck = 0; ck < 4; ck++) {
        __syncthreads();
        // Stage W chunk: pre-interleaved, pure float4 copies (4 iters)
        const float* wsrc = wprep + ((size_t)(mat * 4 + ck) * 128) * 32;
        for (int i = t; i < 1024; i += 256) {
            int n   = i >> 3;
            int kp4 = (i & 7) << 2;
            *(float4*)&Wp[(size_t)n * KS_STRIDE + kp4] =
                *(const float4*)&wsrc[(size_t)n * 32 + kp4];
        }
        // Stage A chunk: 512 groups of 8 consecutive k (2 iters)
        for (int i = t; i < 512; i += 256) {
            int m = i >> 2;                  // 0..127
            int g = i & 3;                   // 8-k group
            float va[8];
            if (AHALF) {
                F8 v = {};
                if (m0 + m < M)
                    v = ldh8((const __half*)Av + (size_t)(m0 + m) * 128 + ck * 32 + g * 8);
#pragma unroll
                for (int j = 0; j < 8; j++) va[j] = v.v[j];  // fp16 exact in tf32
            } else {
                float4 v0 = make_float4(0.f,0.f,0.f,0.f), v1 = v0;
                if (m0 + m < M) {
                    const float* ap = (const float*)Av + (size_t)(m0 + m) * 128 + ck * 32 + g * 8;
                    v0 = *(const float4*)ap;
                    v1 = *(const float4*)(ap + 4);
                }
                va[0] = __uint_as_float(f2tf32(v0.x)); va[1] = __uint_as_float(f2tf32(v0.y));
                va[2] = __uint_as_float(f2tf32(v0.z)); va[3] = __uint_as_float(f2tf32(v0.w));
                va[4] = __uint_as_float(f2tf32(v1.x)); va[5] = __uint_as_float(f2tf32(v1.y));
                va[6] = __uint_as_float(f2tf32(v1.z)); va[7] = __uint_as_float(f2tf32(v1.w));
            }
            float* ap = &Ap[(size_t)m * KS_STRIDE + g * 8];
#pragma unroll
            for (int j = 0; j < 4; j++)      // pair (k, k+4) -> words (2j, 2j+1)
                *(float2*)&ap[j * 2] = make_float2(va[j], va[j + 4]);
        }
        __syncthreads();

#pragma unroll
        for (int ks = 0; ks < 4; ks++) {
            const int kb = ks * 8 + tg * 2;
            uint32_t b0[4], b1[4];
#pragma unroll
            for (int nt = 0; nt < 4; nt++) {
                int col = wn * 32 + nt * 8 + gid;
                float2 b = *(const float2*)&Wp[(size_t)col * KS_STRIDE + kb];
                b0[nt] = __float_as_uint(b.x);
                b1[nt] = __float_as_uint(b.y);
            }
#pragma unroll
            for (int mt = 0; mt < 4; mt++) {
                int row = wm * 64 + mt * 16 + gid;
                float2 a02 = *(const float2*)&Ap[(size_t)row * KS_STRIDE + kb];
                float2 a13 = *(const float2*)&Ap[(size_t)(row + 8) * KS_STRIDE + kb];
                uint32_t a0 = __float_as_uint(a02.x);
                uint32_t a2 = __float_as_uint(a02.y);
                uint32_t a1 = __float_as_uint(a13.x);
                uint32_t a3 = __float_as_uint(a13.y);
#pragma unroll
                for (int nt = 0; nt < 4; nt++)
                    mma_tf32(c[mt][nt], a0, a1, a2, a3, b0[nt], b1[nt]);
            }
        }
    }

    // Epilogue: fp16 output
#pragma unroll
    for (int mt = 0; mt < 4; mt++) {
        int r0 = m0 + wm * 64 + mt * 16 + gid;
#pragma unroll
        for (int nt = 0; nt < 4; nt++) {
            int col = wn * 32 + nt * 8 + tg * 2;
            float bx = 0.f, by = 0.f;
            if (BIAS) { bx = __ldg(&bias[col]); by = __ldg(&bias[col + 1]); }
            if (r0 < M)
                *(__half2*)&C[(size_t)r0 * 128 + col] =
                    __floats2half2_rn(c[mt][nt].x + bx, c[mt][nt].y + by);
            if (r0 + 8 < M)
                *(__half2*)&C[(size_t)(r0 + 8) * 128 + col] =
                    __floats2half2_rn(c[mt][nt].z + bx, c[mt][nt].w + by);
        }
    }
}

// ---------------------------------------------------------------------------
// GCN gather: 16 lanes per node (2 nodes/warp), 16B loads, unroll-4,
// fused bias + relu. fp16 io, fp32 accum. (No shuffles -> divergence-safe.)
// ---------------------------------------------------------------------------
__global__ __launch_bounds__(256) void gcn_gather_kernel(
    const __half* __restrict__ xw, const int* __restrict__ offs,
    const int* __restrict__ csr, const float* __restrict__ dinv,
    const float* __restrict__ bias, __half* __restrict__ out)
{
    int node = (blockIdx.x * 256 + threadIdx.x) >> 4;
    int co   = (threadIdx.x & 15) * 8;
    if (node >= NNODES) return;
    int s = __ldg(&offs[node]);
    int e = __ldg(&offs[node + 1]);
    float dr = __ldg(&dinv[node]);

    float a0[8] = {0,0,0,0,0,0,0,0}, a1[8] = {0,0,0,0,0,0,0,0};
    int p = s;
    for (; p + 4 <= e; p += 4) {
        int c0 = __ldg(&csr[p + 0]) & 0x7fffffff;
        int c1 = __ldg(&csr[p + 1]) & 0x7fffffff;
        int c2 = __ldg(&csr[p + 2]) & 0x7fffffff;
        int c3 = __ldg(&csr[p + 3]) & 0x7fffffff;
        float n0 = dr * __ldg(&dinv[c0]);
        float n1 = dr * __ldg(&dinv[c1]);
        float n2 = dr * __ldg(&dinv[c2]);
        float n3 = dr * __ldg(&dinv[c3]);
        F8 v0 = ldh8(xw + (size_t)c0 * 128 + co);
        F8 v1 = ldh8(xw + (size_t)c1 * 128 + co);
        F8 v2 = ldh8(xw + (size_t)c2 * 128 + co);
        F8 v3 = ldh8(xw + (size_t)c3 * 128 + co);
#pragma unroll
        for (int j = 0; j < 8; j++) {
            a0[j] = fmaf(v0.v[j], n0, a0[j]);
            a1[j] = fmaf(v1.v[j], n1, a1[j]);
            a0[j] = fmaf(v2.v[j], n2, a0[j]);
            a1[j] = fmaf(v3.v[j], n3, a1[j]);
        }
    }
    for (; p < e; p++) {
        int c0 = __ldg(&csr[p]) & 0x7fffffff;
        float n0 = dr * __ldg(&dinv[c0]);
        F8 v0 = ldh8(xw + (size_t)c0 * 128 + co);
#pragma unroll
        for (int j = 0; j < 8; j++) a0[j] = fmaf(v0.v[j], n0, a0[j]);
    }
    float4 b0 = *(const float4*)&bias[co];
    float4 b1 = *(const float4*)&bias[co + 4];
    float bb[8] = {b0.x, b0.y, b0.z, b0.w, b1.x, b1.y, b1.z, b1.w};
    float r[8];
#pragma unroll
    for (int j = 0; j < 8; j++) r[j] = fmaxf(a0[j] + a1[j] + bb[j], 0.0f);
    sth8(out + (size_t)node * 128 + co, r);
}

// ---------------------------------------------------------------------------
// GAT gather: 16 lanes per node (2 nodes/warp), 4-step shfl reduce with the
// GROUP mask (0xFFFF << (lane & 16)) — the two 16-lane groups process
// different nodes with different trip counts, so full-warp masks are illegal.
// Two interleaved online-softmax states. fp16 io, fp32 math.
// ---------------------------------------------------------------------------
__global__ __launch_bounds__(256) void gat_gather_kernel(
    const __half* __restrict__ h, const int* __restrict__ offs,
    const int* __restrict__ csr, __half* __restrict__ out)
{
    int node = (blockIdx.x * 256 + threadIdx.x) >> 4;
    int co   = (threadIdx.x & 15) * 8;
    const unsigned gmask = 0xFFFFu << (threadIdx.x & 16);   // this 16-lane group
    if (node >= NNODES) return;
    int s = __ldg(&offs[node]);
    int e = __ldg(&offs[node + 1]);

    F8 hr = ldh8(h + (size_t)node * 128 + co);

    float m0 = -INFINITY, d0 = 0.0f;
    float m1 = -INFINITY, d1 = 0.0f;
    float a0[8] = {0,0,0,0,0,0,0,0}, a1[8] = {0,0,0,0,0,0,0,0};

    int p = s;
    for (; p + 2 <= e; p += 2) {
        int r0 = __ldg(&csr[p]);
        int r1 = __ldg(&csr[p + 1]);
        F8 h0 = ldh8(h + (size_t)(r0 & 0x7fffffff) * 128 + co);
        F8 h1 = ldh8(h + (size_t)(r1 & 0x7fffffff) * 128 + co);
        float t0 = 0.f, t1 = 0.f;
#pragma unroll
        for (int j = 0; j < 8; j++) {
            t0 = fmaf(h0.v[j], hr.v[j], t0);
            t1 = fmaf(h1.v[j], hr.v[j], t1);
        }
#pragma unroll
        for (int sh = 8; sh; sh >>= 1) {       // stays within 16-lane group
            t0 += __shfl_xor_sync(gmask, t0, sh);
            t1 += __shfl_xor_sync(gmask, t1, sh);
        }
        if (r0 >= 0) {
            float al = (t0 >= 0.f) ? t0 : 0.2f * t0;
            if (al > m0) {
                float sc = __expf(m0 - al);
                d0 *= sc;
#pragma unroll
                for (int j = 0; j < 8; j++) a0[j] *= sc;
                m0 = al;
            }
            float w = __expf(al - m0);
            d0 += w;
#pragma unroll
            for (int j = 0; j < 8; j++) a0[j] = fmaf(h0.v[j], w, a0[j]);
        }
        if (r1 >= 0) {
            float al = (t1 >= 0.f) ? t1 : 0.2f * t1;
            if (al > m1) {
                float sc = __expf(m1 - al);
                d1 *= sc;
#pragma unroll
                for (int j = 0; j < 8; j++) a1[j] *= sc;
                m1 = al;
            }
            float w = __expf(al - m1);
            d1 += w;
#pragma unroll
            for (int j = 0; j < 8; j++) a1[j] = fmaf(h1.v[j], w, a1[j]);
        }
    }
    if (p < e) {
        int r0 = __ldg(&csr[p]);
        F8 h0 = ldh8(h + (size_t)(r0 & 0x7fffffff) * 128 + co);
        float t0 = 0.f;
#pragma unroll
        for (int j = 0; j < 8; j++) t0 = fmaf(h0.v[j], hr.v[j], t0);
#pragma unroll
        for (int sh = 8; sh; sh >>= 1) t0 += __shfl_xor_sync(gmask, t0, sh);
        if (r0 >= 0) {
            float al = (t0 >= 0.f) ? t0 : 0.2f * t0;
            if (al > m0) {
                float sc = __expf(m0 - al);
                d0 *= sc;
#pragma unroll
                for (int j = 0; j < 8; j++) a0[j] *= sc;
                m0 = al;
            }
            float w = __expf(al - m0);
            d0 += w;
#pragma unroll
            for (int j = 0; j < 8; j++) a0[j] = fmaf(h0.v[j], w, a0[j]);
        }
    }

    // Merge the two states (self loop always valid -> at least one non-empty)
    float M_ = fmaxf(m0, m1);
    float s0 = __expf(m0 - M_);
    float s1 = __expf(m1 - M_);
    float den = d0 * s0 + d1 * s1;
    float inv = 1.0f / fmaxf(den, 1e-16f);
    float r[8];
#pragma unroll
    for (int j = 0; j < 8; j++) r[j] = (a0[j] * s0 + a1[j] * s1) * inv;
    sth8(out + (size_t)node * 128 + co, r);
}

// ---------------------------------------------------------------------------
// Global mean pool: fused colsum + writeout (last block writes d_out).
// ---------------------------------------------------------------------------
__global__ __launch_bounds__(256) void colsum_kernel(
    const __half* __restrict__ h, float* __restrict__ acc, float* __restrict__ out)
{
    __shared__ float sm[16][HDIM];
    __shared__ int last;
    int t  = threadIdx.x;
    int co = (t & 15) * 8;
    int rg = t >> 4;                         // 0..15
    int start = blockIdx.x * COL_CHUNK;
    int end   = start + COL_CHUNK;
    if (end > NNODES) end = NNODES;

    float s[8] = {0,0,0,0,0,0,0,0};
    for (int r = start + rg; r < end; r += 16) {
        F8 v = ldh8(h + (size_t)r * 128 + co);
#pragma unroll
        for (int j = 0; j < 8; j++) s[j] += v.v[j];
    }
#pragma unroll
    for (int j = 0; j < 8; j++) sm[rg][co + j] = s[j];
    __syncthreads();
    if (t < HDIM) {
        float tot = 0.f;
#pragma unroll
        for (int g = 0; g < 16; g++) tot += sm[g][t];
        atomicAdd(&acc[t], tot);
    }
    __threadfence();
    __syncthreads();
    if (t == 0) {
        int done = atomicAdd(&g_ctr, 1);
        last = (done == COL_NB - 1) ? 1 : 0;
    }
    __syncthreads();
    if (last) {
        float v = __ldcg(&acc[t & 127]);     // L1-bypass: see peers' atomics
        out[t] = v * (1.0f / (float)NNODES);
        if (t == 0) g_ctr = 0;               // reset for next replay
    }
}

// ---------------------------------------------------------------------------
// Launch
// ---------------------------------------------------------------------------
extern "C" void kernel_launch(void* const* d_in, const int* in_sizes, int n_in,
                              void* d_out, int out_size)
{
    const float* x  = (const float*)d_in[0];
    const void*  ei = d_in[1];
    const float* Wg[3] = {(const float*)d_in[2], (const float*)d_in[6],  (const float*)d_in[10]};
    const float* bg[3] = {(const float*)d_in[3], (const float*)d_in[7],  (const float*)d_in[11]};
    const float* Wa[3] = {(const float*)d_in[4], (const float*)d_in[8],  (const float*)d_in[12]};
    const float* ba[3] = {(const float*)d_in[5], (const float*)d_in[9],  (const float*)d_in[13]};

    __half *h0, *h1;
    float *dinv, *acc, *wprep;
    int *csr, *cnt, *offs, *cur, *bsum;
    cudaGetSymbolAddress((void**)&h0,   g_h0);
    cudaGetSymbolAddress((void**)&h1,   g_h1);
    cudaGetSymbolAddress((void**)&dinv, g_dinv);
    cudaGetSymbolAddress((void**)&acc,  g_acc);
    cudaGetSymbolAddress((void**)&wprep,g_wprep);
    cudaGetSymbolAddress((void**)&csr,  g_csr);
    cudaGetSymbolAddress((void**)&cnt,  g_cnt);
    cudaGetSymbolAddress((void**)&offs, g_offs);
    cudaGetSymbolAddress((void**)&cur,  g_cur);
    cudaGetSymbolAddress((void**)&bsum, g_bsum);

    const int NB_E    = (NEDGES + 255) / 256;
    const int NB_ET   = (ETOT + 255) / 256;
    const int NB_GATH = (NNODES * 16 + 255) / 256;   // 16 lanes per node
    const int NB_GEMM = (NNODES + 127) / 128;        // 313

    // Weight prep (independent)
    wprep_kernel<<<6, 256>>>(Wg[0], Wa[0], Wg[1], Wa[1], Wg[2], Wa[2], wprep);

    // CSR build
    detect_zero_kernel<<<SCAN_NB, 1024>>>(ei, cnt);
    cnt_acc_kernel<<<NB_E, 256>>>(ei, cnt);
    scan1_kernel<<<SCAN_NB, 1024>>>(cnt, offs, bsum, acc);
    scan3_kernel<<<SCAN_NB, 1024>>>(cnt, bsum, offs, cur, dinv);
    csr_scatter_kernel<<<NB_ET, 256>>>(ei, cur, csr);

    for (int l = 0; l < 3; l++) {
        // --- GCN: GEMM -> gather(+bias+relu) ---
        if (l == 0)
            mm_tf32_k128<false, false><<<NB_GEMM, 256>>>(x,  wprep, 0,     nullptr, h0, NNODES);
        else
            mm_tf32_k128<true,  false><<<NB_GEMM, 256>>>(h1, wprep, l * 2, nullptr, h0, NNODES);
        gcn_gather_kernel<<<NB_GATH, 256>>>(h0, offs, csr, dinv, bg[l], h1);

        // --- GAT: GEMM(+bias) -> fused online-softmax gather ---
        mm_tf32_k128<true, true><<<NB_GEMM, 256>>>(h1, wprep, l * 2 + 1, ba[l], h0, NNODES);
        gat_gather_kernel<<<NB_GATH, 256>>>(h0, offs, csr, h1);
    }

    // Global mean pool (concat halves identical); h1 holds final features
    colsum_kernel<<<COL_NB, 256>>>(h1, acc, (float*)d_out);
}

// round 10
// speedup vs baseline: 1.8290x; 1.0943x over previous
#include <cuda_runtime.h>
#include <cuda_fp16.h>
#include <math.h>
#include <stdint.h>

// Problem constants
#define NNODES 40000
#define NEDGES 640000
#define ETOT   (NEDGES + NNODES)   // edges + appended self loops
#define HDIM   128
#define SCAN_NB 40                 // ceil(NNODES / 1024)
#define COL_NB  128                // colsum grid
#define COL_CHUNK 313              // ceil(NNODES / COL_NB)

// ---------------------------------------------------------------------------
// Scratch (device globals; no allocation allowed in kernel_launch)
// ---------------------------------------------------------------------------
__device__ __align__(16) __half g_h0[(size_t)NNODES * HDIM];  // 10.25 MB
__device__ __align__(16) __half g_h1[(size_t)NNODES * HDIM];  // 10.25 MB
__device__ int   g_csr[ETOT];            // packed: col | (invalid << 31)
__device__ int   g_cnt[NNODES];          // edge count per row (excl. self loop)
__device__ int   g_offs[NNODES + 1];
__device__ int   g_cur[NNODES];
__device__ int   g_bsum[64];
__device__ float g_dinv[NNODES];
__device__ float g_acc[HDIM];
__device__ int   g_ctr;                  // colsum completion counter
__device__ float g_wprep[6 * 128 * 32 * 4];  // 6 tf32-interleaved Weff, 393KB
__device__ int   g_is64;

// ---------------------------------------------------------------------------
// fp16 helpers: 8 features (16 B) per lane
// ---------------------------------------------------------------------------
struct F8 { float v[8]; };
__device__ __forceinline__ F8 ldh8(const __half* p) {
    uint4 u = *(const uint4*)p;
    F8 r; float2 f;
    f = __half22float2(*(__half2*)&u.x); r.v[0] = f.x; r.v[1] = f.y;
    f = __half22float2(*(__half2*)&u.y); r.v[2] = f.x; r.v[3] = f.y;
    f = __half22float2(*(__half2*)&u.z); r.v[4] = f.x; r.v[5] = f.y;
    f = __half22float2(*(__half2*)&u.w); r.v[6] = f.x; r.v[7] = f.y;
    return r;
}
__device__ __forceinline__ void sth8(__half* p, const float* v) {
    uint4 u;
    *(__half2*)&u.x = __floats2half2_rn(v[0], v[1]);
    *(__half2*)&u.y = __floats2half2_rn(v[2], v[3]);
    *(__half2*)&u.z = __floats2half2_rn(v[4], v[5]);
    *(__half2*)&u.w = __floats2half2_rn(v[6], v[7]);
    *(uint4*)p = u;
}

// ---------------------------------------------------------------------------
// detect dtype (block 0) + zero cnt (all blocks). edge_index is logically
// int64 [2,E] but may be int32 physically (JAX x64 off).
// ---------------------------------------------------------------------------
__global__ __launch_bounds__(1024) void detect_zero_kernel(const void* ei, int* cnt) {
    int i = blockIdx.x * 1024 + threadIdx.x;
    if (i < NNODES) cnt[i] = 0;
    if (blockIdx.x == 0) {
        __shared__ int ok;
        if (threadIdx.x == 0) ok = 1;
        __syncthreads();
        const long long* p = (const long long*)ei;
        long long v = p[threadIdx.x];      // 1024 samples
        if (v < 0 || v >= NNODES) atomicAnd(&ok, 0);
        __syncthreads();
        if (threadIdx.x == 0) g_is64 = ok;
    }
}

__global__ void cnt_acc_kernel(const void* ei, int* cnt) {
    int e = blockIdx.x * blockDim.x + threadIdx.x;
    if (e >= NEDGES) return;
    int r = g_is64 ? (int)((const long long*)ei)[e] : ((const int*)ei)[e];
    atomicAdd(&cnt[r], 1);
}

// Phase 1: per-block (1024) exclusive scan of deg = cnt+1; block totals.
// Block 0 also zeroes g_acc for the final pool.
__global__ __launch_bounds__(1024) void scan1_kernel(
    const int* __restrict__ cnt, int* __restrict__ excl, int* __restrict__ bsum,
    float* __restrict__ acc)
{
    __shared__ int wsum[32];
    int t = threadIdx.x;
    int i = blockIdx.x * 1024 + t;
    int lane = t & 31, w = t >> 5;
    if (blockIdx.x == 0 && t < HDIM) acc[t] = 0.0f;
    int v = (i < NNODES) ? (cnt[i] + 1) : 0;    // +1 = appended self loop
    int s = v;
#pragma unroll
    for (int d = 1; d < 32; d <<= 1) {
        int u = __shfl_up_sync(0xffffffffu, s, d);
        if (lane >= d) s += u;
    }
    if (lane == 31) wsum[w] = s;
    __syncthreads();
    if (w == 0) {
        int ws = wsum[lane];
#pragma unroll
        for (int d = 1; d < 32; d <<= 1) {
            int u = __shfl_up_sync(0xffffffffu, ws, d);
            if (lane >= d) ws += u;
        }
        wsum[lane] = ws;
    }
    __syncthreads();
    int incl = s + (w ? wsum[w - 1] : 0);
    if (i < NNODES) excl[i] = incl - v;
    if (t == 0) bsum[blockIdx.x] = wsum[31];
}

// Phase 2+3 merged: each block prefix-sums bsum locally, finalizes offsets.
__global__ __launch_bounds__(1024) void scan3_kernel(
    const int* __restrict__ cnt, const int* __restrict__ bsum,
    int* __restrict__ offs, int* __restrict__ cur, float* __restrict__ dinv)
{
    __shared__ int base;
    if (threadIdx.x == 0) {
        int run = 0;
        for (int b = 0; b < (int)blockIdx.x; b++) run += bsum[b];
        base = run;
    }
    __syncthreads();
    int i = blockIdx.x * 1024 + threadIdx.x;
    if (i < NNODES) {
        int off = offs[i] + base;
        offs[i] = off;
        cur[i]  = off;
        dinv[i] = rsqrtf((float)(cnt[i] + 1));
    }
    if (i == 0) offs[NNODES] = ETOT;
}

__global__ void csr_scatter_kernel(const void* ei, int* cur, int* csr) {
    int e = blockIdx.x * blockDim.x + threadIdx.x;
    if (e >= ETOT) return;
    int r, c, invalid = 0;
    if (e < NEDGES) {
        if (g_is64) {
            const long long* p = (const long long*)ei;
            r = (int)p[e]; c = (int)p[NEDGES + e];
        } else {
            const int* p = (const int*)ei;
            r = p[e]; c = p[NEDGES + e];
        }
        if (r == c) invalid = (int)0x80000000;  // masked for GAT, kept for GCN
    } else {
        r = c = e - NEDGES;
    }
    int pos = atomicAdd(&cur[r], 1);
    csr[pos] = c | invalid;
}

// ---------------------------------------------------------------------------
// Weight prep: all 6 effective weights -> tf32, kpos8-interleaved, once.
// g_wprep[((mat*4 + ck)*128 + n)*32 + kpos8(k&31)].
// mats: 0=Wg0, 1=Wa0, 2=Wg1(+fold), 3=Wa1, 4=Wg2(+fold), 5=Wa2
// ---------------------------------------------------------------------------
__device__ __forceinline__ uint32_t f2tf32(float v) {
    uint32_t r;
    asm("cvt.rna.tf32.f32 %0, %1;" : "=r"(r) : "f"(v));
    return r;
}
__device__ __forceinline__ int kpos8(int k) {   // k in [0,32)
    return (k >> 3) * 8 + (k & 3) * 2 + ((k >> 2) & 1);
}

__global__ void wprep_kernel(const float* Wg0, const float* Wa0,
                             const float* Wg1, const float* Wa1,
                             const float* Wg2, const float* Wa2,
                             float* out)
{
    int m = blockIdx.x;
    const float* W; bool add;
    switch (m) {
        case 0: W = Wg0; add = false; break;
        case 1: W = Wa0; add = false; break;
        case 2: W = Wg1; add = true;  break;
        case 3: W = Wa1; add = false; break;
        case 4: W = Wg2; add = true;  break;
        default: W = Wa2; add = false; break;
    }
    for (int i = threadIdx.x; i < 128 * 128; i += blockDim.x) {
        int n = i & 127, k = i >> 7;
        float v = W[(size_t)k * 128 + n];
        if (add) v += W[(size_t)(k + 128) * 128 + n];
        int ck = k >> 5, kp = kpos8(k & 31);
        out[(((size_t)(m * 4 + ck) * 128 + n) * 32) + kp] = __uint_as_float(f2tf32(v));
    }
}

// ---------------------------------------------------------------------------
// tf32 tensor-core GEMM: C[M,128] = A[M,128] @ Weff[128,128] (+bias|rowscale).
// 256 threads (8 warps, 2 along M x 4 along N), warp tile 64x32.
// SCALE: multiply each output row by dinv[row] (folds GCN symmetric norm).
// ---------------------------------------------------------------------------
#define KS_STRIDE 40

__device__ __forceinline__ void mma_tf32(float4& c, uint32_t a0, uint32_t a1,
                                         uint32_t a2, uint32_t a3,
                                         uint32_t b0, uint32_t b1) {
    asm volatile(
        "mma.sync.aligned.m16n8k8.row.col.f32.tf32.tf32.f32 "
        "{%0,%1,%2,%3}, {%4,%5,%6,%7}, {%8,%9}, {%0,%1,%2,%3};"
        : "+f"(c.x), "+f"(c.y), "+f"(c.z), "+f"(c.w)
        : "r"(a0), "r"(a1), "r"(a2), "r"(a3), "r"(b0), "r"(b1));
}

template<bool AHALF, bool BIAS, bool SCALE>
__global__ __launch_bounds__(256) void mm_tf32_k128(
    const void* __restrict__ Av, const float* __restrict__ wprep, int mat,
    const float* __restrict__ bias, const float* __restrict__ rs,
    __half* __restrict__ C, int M)
{
    __shared__ float Wp[128 * KS_STRIDE];   // [n=128][kpos 0..31]
    __shared__ float Ap[128 * KS_STRIDE];   // [m=128][kpos 0..31]

    const int t    = threadIdx.x;
    const int warp = t >> 5;
    const int lane = t & 31;
    const int gid  = lane >> 2;             // 0..7
    const int tg   = lane & 3;              // 0..3
    const int wm   = warp & 1;              // 2 warps along M (64 rows each)
    const int wn   = warp >> 1;             // 4 warps along N (32 cols each)
    const int m0   = blockIdx.x * 128;

    float4 c[4][4];
#pragma unroll
    for (int i = 0; i < 4; i++)
#pragma unroll
        for (int j = 0; j < 4; j++) c[i][j] = make_float4(0.f, 0.f, 0.f, 0.f);

    for (int ck = 0; ck < 4; ck++) {
        __syncthreads();
        // Stage W chunk: pre-interleaved, pure float4 copies (4 iters)
        const float* wsrc = wprep + ((size_t)(mat * 4 + ck) * 128) * 32;
        for (int i = t; i < 1024; i += 256) {
            int n   = i >> 3;
            int kp4 = (i & 7) << 2;
            *(float4*)&Wp[(size_t)n * KS_STRIDE + kp4] =
                *(const float4*)&wsrc[(size_t)n * 32 + kp4];
        }
        // Stage A chunk: 512 groups of 8 consecutive k (2 iters)
        for (int i = t; i < 512; i += 256) {
            int m = i >> 2;                  // 0..127
            int g = i & 3;                   // 8-k group
            float va[8];
            if (AHALF) {
                F8 v = {};
                if (m0 + m < M)
                    v = ldh8((const __half*)Av + (size_t)(m0 + m) * 128 + ck * 32 + g * 8);
#pragma unroll
                for (int j = 0; j < 8; j++) va[j] = v.v[j];  // fp16 exact in tf32
            } else {
                float4 v0 = make_float4(0.f,0.f,0.f,0.f), v1 = v0;
                if (m0 + m < M) {
                    const float* ap = (const float*)Av + (size_t)(m0 + m) * 128 + ck * 32 + g * 8;
                    v0 = *(const float4*)ap;
                    v1 = *(const float4*)(ap + 4);
                }
                va[0] = __uint_as_float(f2tf32(v0.x)); va[1] = __uint_as_float(f2tf32(v0.y));
                va[2] = __uint_as_float(f2tf32(v0.z)); va[3] = __uint_as_float(f2tf32(v0.w));
                va[4] = __uint_as_float(f2tf32(v1.x)); va[5] = __uint_as_float(f2tf32(v1.y));
                va[6] = __uint_as_float(f2tf32(v1.z)); va[7] = __uint_as_float(f2tf32(v1.w));
            }
            float* ap = &Ap[(size_t)m * KS_STRIDE + g * 8];
#pragma unroll
            for (int j = 0; j < 4; j++)      // pair (k, k+4) -> words (2j, 2j+1)
                *(float2*)&ap[j * 2] = make_float2(va[j], va[j + 4]);
        }
        __syncthreads();

#pragma unroll
        for (int ks = 0; ks < 4; ks++) {
            const int kb = ks * 8 + tg * 2;
            uint32_t b0[4], b1[4];
#pragma unroll
            for (int nt = 0; nt < 4; nt++) {
                int col = wn * 32 + nt * 8 + gid;
                float2 b = *(const float2*)&Wp[(size_t)col * KS_STRIDE + kb];
                b0[nt] = __float_as_uint(b.x);
                b1[nt] = __float_as_uint(b.y);
            }
#pragma unroll
            for (int mt = 0; mt < 4; mt++) {
                int row = wm * 64 + mt * 16 + gid;
                float2 a02 = *(const float2*)&Ap[(size_t)row * KS_STRIDE + kb];
                float2 a13 = *(const float2*)&Ap[(size_t)(row + 8) * KS_STRIDE + kb];
                uint32_t a0 = __float_as_uint(a02.x);
                uint32_t a2 = __float_as_uint(a02.y);
                uint32_t a1 = __float_as_uint(a13.x);
                uint32_t a3 = __float_as_uint(a13.y);
#pragma unroll
                for (int nt = 0; nt < 4; nt++)
                    mma_tf32(c[mt][nt], a0, a1, a2, a3, b0[nt], b1[nt]);
            }
        }
    }

    // Epilogue: optional per-row scale (GCN norm fold) or bias; fp16 output
#pragma unroll
    for (int mt = 0; mt < 4; mt++) {
        int r0 = m0 + wm * 64 + mt * 16 + gid;
        float s0 = 1.f, s1 = 1.f;
        if (SCALE) {
            if (r0 < M)     s0 = __ldg(&rs[r0]);
            if (r0 + 8 < M) s1 = __ldg(&rs[r0 + 8]);
        }
#pragma unroll
        for (int nt = 0; nt < 4; nt++) {
            int col = wn * 32 + nt * 8 + tg * 2;
            float bx = 0.f, by = 0.f;
            if (BIAS) { bx = __ldg(&bias[col]); by = __ldg(&bias[col + 1]); }
            if (r0 < M)
                *(__half2*)&C[(size_t)r0 * 128 + col] =
                    __floats2half2_rn(c[mt][nt].x * s0 + bx, c[mt][nt].y * s0 + by);
            if (r0 + 8 < M)
                *(__half2*)&C[(size_t)(r0 + 8) * 128 + col] =
                    __floats2half2_rn(c[mt][nt].z * s1 + bx, c[mt][nt].w * s1 + by);
        }
    }
}

// ---------------------------------------------------------------------------
// GCN gather: 16 lanes per node (2 nodes/warp). Input rows are PRE-SCALED by
// dinv[c] (GEMM epilogue), so the loop is a pure sum of neighbor rows:
// out = relu(dinv_r * sum + bias). Unroll 4, no per-edge dinv load/multiply.
// ---------------------------------------------------------------------------
__global__ __launch_bounds__(256) void gcn_gather_kernel(
    const __half* __restrict__ xw, const int* __restrict__ offs,
    const int* __restrict__ csr, const float* __restrict__ dinv,
    const float* __restrict__ bias, __half* __restrict__ out)
{
    int node = (blockIdx.x * 256 + threadIdx.x) >> 4;
    int co   = (threadIdx.x & 15) * 8;
    if (node >= NNODES) return;
    int s = __ldg(&offs[node]);
    int e = __ldg(&offs[node + 1]);
    float dr = __ldg(&dinv[node]);

    float a0[8] = {0,0,0,0,0,0,0,0}, a1[8] = {0,0,0,0,0,0,0,0};
    int p = s;
    for (; p + 4 <= e; p += 4) {
        int c0 = __ldg(&csr[p + 0]) & 0x7fffffff;
        int c1 = __ldg(&csr[p + 1]) & 0x7fffffff;
        int c2 = __ldg(&csr[p + 2]) & 0x7fffffff;
        int c3 = __ldg(&csr[p + 3]) & 0x7fffffff;
        F8 v0 = ldh8(xw + (size_t)c0 * 128 + co);
        F8 v1 = ldh8(xw + (size_t)c1 * 128 + co);
        F8 v2 = ldh8(xw + (size_t)c2 * 128 + co);
        F8 v3 = ldh8(xw + (size_t)c3 * 128 + co);
#pragma unroll
        for (int j = 0; j < 8; j++) {
            a0[j] += v0.v[j] + v2.v[j];
            a1[j] += v1.v[j] + v3.v[j];
        }
    }
    for (; p < e; p++) {
        int c0 = __ldg(&csr[p]) & 0x7fffffff;
        F8 v0 = ldh8(xw + (size_t)c0 * 128 + co);
#pragma unroll
        for (int j = 0; j < 8; j++) a0[j] += v0.v[j];
    }
    float4 b0 = *(const float4*)&bias[co];
    float4 b1 = *(const float4*)&bias[co + 4];
    float bb[8] = {b0.x, b0.y, b0.z, b0.w, b1.x, b1.y, b1.z, b1.w};
    float r[8];
#pragma unroll
    for (int j = 0; j < 8; j++)
        r[j] = fmaxf(fmaf(a0[j] + a1[j], dr, bb[j]), 0.0f);
    sth8(out + (size_t)node * 128 + co, r);
}

// ---------------------------------------------------------------------------
// GAT gather: 16 lanes per node (2 nodes/warp), 4-step shfl reduce with the
// GROUP mask (0xFFFF << (lane & 16)). Softmax WITHOUT max-subtraction:
// logits are O(+-25) worst case (dots of O(0.6)-rms features over 128 dims),
// exp() cannot overflow fp32, and exp(a)/sum == exp(a-m)/sum(exp(a-m)).
// Unroll 4: independent dot chains, no serial rescale state.
// ---------------------------------------------------------------------------
__global__ __launch_bounds__(256) void gat_gather_kernel(
    const __half* __restrict__ h, const int* __restrict__ offs,
    const int* __restrict__ csr, __half* __restrict__ out)
{
    int node = (blockIdx.x * 256 + threadIdx.x) >> 4;
    int co   = (threadIdx.x & 15) * 8;
    const unsigned gmask = 0xFFFFu << (threadIdx.x & 16);   // this 16-lane group
    if (node >= NNODES) return;
    int s = __ldg(&offs[node]);
    int e = __ldg(&offs[node + 1]);

    F8 hr = ldh8(h + (size_t)node * 128 + co);

    float den = 0.0f;
    float a0[8] = {0,0,0,0,0,0,0,0}, a1[8] = {0,0,0,0,0,0,0,0};

    int p = s;
    for (; p + 4 <= e; p += 4) {
        int r0 = __ldg(&csr[p + 0]);
        int r1 = __ldg(&csr[p + 1]);
        int r2 = __ldg(&csr[p + 2]);
        int r3 = __ldg(&csr[p + 3]);
        F8 h0 = ldh8(h + (size_t)(r0 & 0x7fffffff) * 128 + co);
        F8 h1 = ldh8(h + (size_t)(r1 & 0x7fffffff) * 128 + co);
        F8 h2 = ldh8(h + (size_t)(r2 & 0x7fffffff) * 128 + co);
        F8 h3 = ldh8(h + (size_t)(r3 & 0x7fffffff) * 128 + co);
        float t0 = 0.f, t1 = 0.f, t2 = 0.f, t3 = 0.f;
#pragma unroll
        for (int j = 0; j < 8; j++) {
            t0 = fmaf(h0.v[j], hr.v[j], t0);
            t1 = fmaf(h1.v[j], hr.v[j], t1);
            t2 = fmaf(h2.v[j], hr.v[j], t2);
            t3 = fmaf(h3.v[j], hr.v[j], t3);
        }
#pragma unroll
        for (int sh = 8; sh; sh >>= 1) {
            t0 += __shfl_xor_sync(gmask, t0, sh);
            t1 += __shfl_xor_sync(gmask, t1, sh);
            t2 += __shfl_xor_sync(gmask, t2, sh);
            t3 += __shfl_xor_sync(gmask, t3, sh);
        }
        float w0 = (r0 >= 0) ? __expf((t0 >= 0.f) ? t0 : 0.2f * t0) : 0.f;
        float w1 = (r1 >= 0) ? __expf((t1 >= 0.f) ? t1 : 0.2f * t1) : 0.f;
        float w2 = (r2 >= 0) ? __expf((t2 >= 0.f) ? t2 : 0.2f * t2) : 0.f;
        float w3 = (r3 >= 0) ? __expf((t3 >= 0.f) ? t3 : 0.2f * t3) : 0.f;
        den += (w0 + w1) + (w2 + w3);
#pragma unroll
        for (int j = 0; j < 8; j++) {
            a0[j] = fmaf(h0.v[j], w0, fmaf(h2.v[j], w2, a0[j]));
            a1[j] = fmaf(h1.v[j], w1, fmaf(h3.v[j], w3, a1[j]));
        }
    }
    for (; p < e; p++) {
        int r0 = __ldg(&csr[p]);
        F8 h0 = ldh8(h + (size_t)(r0 & 0x7fffffff) * 128 + co);
        float t0 = 0.f;
#pragma unroll
        for (int j = 0; j < 8; j++) t0 = fmaf(h0.v[j], hr.v[j], t0);
#pragma unroll
        for (int sh = 8; sh; sh >>= 1) t0 += __shfl_xor_sync(gmask, t0, sh);
        float w0 = (r0 >= 0) ? __expf((t0 >= 0.f) ? t0 : 0.2f * t0) : 0.f;
        den += w0;
#pragma unroll
        for (int j = 0; j < 8; j++) a0[j] = fmaf(h0.v[j], w0, a0[j]);
    }

    float inv = 1.0f / fmaxf(den, 1e-16f);   // den >= exp(self-loop) > 0
    float r[8];
#pragma unroll
    for (int j = 0; j < 8; j++) r[j] = (a0[j] + a1[j]) * inv;
    sth8(out + (size_t)node * 128 + co, r);
}

// ---------------------------------------------------------------------------
// Global mean pool: fused colsum + writeout (last block writes d_out).
// ---------------------------------------------------------------------------
__global__ __launch_bounds__(256) void colsum_kernel(
    const __half* __restrict__ h, float* __restrict__ acc, float* __restrict__ out)
{
    __shared__ float sm[16][HDIM];
    __shared__ int last;
    int t  = threadIdx.x;
    int co = (t & 15) * 8;
    int rg = t >> 4;                         // 0..15
    int start = blockIdx.x * COL_CHUNK;
    int end   = start + COL_CHUNK;
    if (end > NNODES) end = NNODES;

    float s[8] = {0,0,0,0,0,0,0,0};
    for (int r = start + rg; r < end; r += 16) {
        F8 v = ldh8(h + (size_t)r * 128 + co);
#pragma unroll
        for (int j = 0; j < 8; j++) s[j] += v.v[j];
    }
#pragma unroll
    for (int j = 0; j < 8; j++) sm[rg][co + j] = s[j];
    __syncthreads();
    if (t < HDIM) {
        float tot = 0.f;
#pragma unroll
        for (int g = 0; g < 16; g++) tot += sm[g][t];
        atomicAdd(&acc[t], tot);
    }
    __threadfence();
    __syncthreads();
    if (t == 0) {
        int done = atomicAdd(&g_ctr, 1);
        last = (done == COL_NB - 1) ? 1 : 0;
    }
    __syncthreads();
    if (last) {
        float v = __ldcg(&acc[t & 127]);     // L1-bypass: see peers' atomics
        out[t] = v * (1.0f / (float)NNODES);
        if (t == 0) g_ctr = 0;               // reset for next replay
    }
}

// ---------------------------------------------------------------------------
// Launch
// ---------------------------------------------------------------------------
extern "C" void kernel_launch(void* const* d_in, const int* in_sizes, int n_in,
                              void* d_out, int out_size)
{
    const float* x  = (const float*)d_in[0];
    const void*  ei = d_in[1];
    const float* Wg[3] = {(const float*)d_in[2], (const float*)d_in[6],  (const float*)d_in[10]};
    const float* bg[3] = {(const float*)d_in[3], (const float*)d_in[7],  (const float*)d_in[11]};
    const float* Wa[3] = {(const float*)d_in[4], (const float*)d_in[8],  (const float*)d_in[12]};
    const float* ba[3] = {(const float*)d_in[5], (const float*)d_in[9],  (const float*)d_in[13]};

    __half *h0, *h1;
    float *dinv, *acc, *wprep;
    int *csr, *cnt, *offs, *cur, *bsum;
    cudaGetSymbolAddress((void**)&h0,   g_h0);
    cudaGetSymbolAddress((void**)&h1,   g_h1);
    cudaGetSymbolAddress((void**)&dinv, g_dinv);
    cudaGetSymbolAddress((void**)&acc,  g_acc);
    cudaGetSymbolAddress((void**)&wprep,g_wprep);
    cudaGetSymbolAddress((void**)&csr,  g_csr);
    cudaGetSymbolAddress((void**)&cnt,  g_cnt);
    cudaGetSymbolAddress((void**)&offs, g_offs);
    cudaGetSymbolAddress((void**)&cur,  g_cur);
    cudaGetSymbolAddress((void**)&bsum, g_bsum);

    const int NB_E    = (NEDGES + 255) / 256;
    const int NB_ET   = (ETOT + 255) / 256;
    const int NB_GATH = (NNODES * 16 + 255) / 256;   // 16 lanes per node
    const int NB_GEMM = (NNODES + 127) / 128;        // 313

    // Weight prep (independent)
    wprep_kernel<<<6, 256>>>(Wg[0], Wa[0], Wg[1], Wa[1], Wg[2], Wa[2], wprep);

    // CSR build
    detect_zero_kernel<<<SCAN_NB, 1024>>>(ei, cnt);
    cnt_acc_kernel<<<NB_E, 256>>>(ei, cnt);
    scan1_kernel<<<SCAN_NB, 1024>>>(cnt, offs, bsum, acc);
    scan3_kernel<<<SCAN_NB, 1024>>>(cnt, bsum, offs, cur, dinv);
    csr_scatter_kernel<<<NB_ET, 256>>>(ei, cur, csr);

    for (int l = 0; l < 3; l++) {
        // --- GCN: GEMM(row-scale by dinv) -> sum-gather(+bias+relu) ---
        if (l == 0)
            mm_tf32_k128<false, false, true><<<NB_GEMM, 256>>>(x,  wprep, 0,     nullptr, dinv, h0, NNODES);
        else
            mm_tf32_k128<true,  false, true><<<NB_GEMM, 256>>>(h1, wprep, l * 2, nullptr, dinv, h0, NNODES);
        gcn_gather_kernel<<<NB_GATH, 256>>>(h0, offs, csr, dinv, bg[l], h1);

        // --- GAT: GEMM(+bias) -> fused softmax gather ---
        mm_tf32_k128<true, true, false><<<NB_GEMM, 256>>>(h1, wprep, l * 2 + 1, ba[l], nullptr, h0, NNODES);
        gat_gather_kernel<<<NB_GATH, 256>>>(h0, offs, csr, h1);
    }

    // Global mean pool (concat halves identical); h1 holds final features
    colsum_kernel<<<COL_NB, 256>>>(h1, acc, (float*)d_out);
}